// round 10
// baseline (speedup 1.0000x reference)
#include <cuda_runtime.h>
#include <cuda_fp16.h>
#include <cstdint>

#define NN 50000
#define NE 600000
#define DD 128

// Scratch (device globals — zero-initialized at module load; aggconv_kernel
// re-zeros g_agg every launch, so agg==0 at every kernel_launch entry).
static __device__ __half g_Yh[(size_t)NN * 256];   // fp16 projections: 0:128 = x@W1a, 128:256 = x@W1b
static __device__ float  g_agg[(size_t)NN * DD];   // fp32 segment sums (atomics)
static __device__ __half g_aggh[(size_t)NN * DD];  // fp16 copy of agg for update GEMM
static __device__ __half g_Xh[(size_t)NN * DD];    // fp16 copy of X
static __device__ __half g_W1t[2 * 128 * 128];     // [half][n][k] fp16 (transposed W1)
static __device__ __half g_W2t[128 * 256];         // [n][k] fp16 (transposed W2)

// ---------------- helpers ----------------
__device__ __forceinline__ void mma_f16(float* d, const uint32_t* a, const uint32_t* b) {
    asm volatile(
        "mma.sync.aligned.m16n8k16.row.col.f32.f16.f16.f32 "
        "{%0,%1,%2,%3}, {%4,%5,%6,%7}, {%8,%9}, {%0,%1,%2,%3};"
        : "+f"(d[0]), "+f"(d[1]), "+f"(d[2]), "+f"(d[3])
        : "r"(a[0]), "r"(a[1]), "r"(a[2]), "r"(a[3]), "r"(b[0]), "r"(b[1]));
}

__device__ __forceinline__ void cp16(uint32_t dst_smem, const void* src, int src_bytes) {
    asm volatile("cp.async.cg.shared.global [%0], [%1], 16, %2;"
                 :: "r"(dst_smem), "l"(src), "r"(src_bytes));
}
__device__ __forceinline__ void cp_commit() { asm volatile("cp.async.commit_group;"); }
template <int N>
__device__ __forceinline__ void cp_wait() { asm volatile("cp.async.wait_group %0;" :: "n"(N)); }

// SMEM layout (fp16, BK=32): row = 32 fp16 + 8 pad = 40 fp16 = 20 words (80B).
#define RS 20                                   // words per row
#define A_STAGE_WORDS (128 * RS)                // 2560
#define B_STAGE_WORDS (128 * RS)                // 2560
#define STAGE_WORDS (A_STAGE_WORDS + B_STAGE_WORDS)  // 5120
#define NSTAGE 3
#define SMEM_BYTES (NSTAGE * STAGE_WORDS * 4)   // 61440

// ---------------- prep: Xh = fp16(X) ----------------
__global__ void convert_x_kernel(const float* __restrict__ X) {
    int i = blockIdx.x * blockDim.x + threadIdx.x;   // one per 8 elements
    if (i >= NN * DD / 8) return;
    const float4* src = reinterpret_cast<const float4*>(X) + i * 2;
    float4 v0 = src[0], v1 = src[1];
    __half2 h0 = __floats2half2_rn(v0.x, v0.y);
    __half2 h1 = __floats2half2_rn(v0.z, v0.w);
    __half2 h2 = __floats2half2_rn(v1.x, v1.y);
    __half2 h3 = __floats2half2_rn(v1.z, v1.w);
    uint4 o;
    o.x = *reinterpret_cast<uint32_t*>(&h0);
    o.y = *reinterpret_cast<uint32_t*>(&h1);
    o.z = *reinterpret_cast<uint32_t*>(&h2);
    o.w = *reinterpret_cast<uint32_t*>(&h3);
    reinterpret_cast<uint4*>(g_Xh)[i] = o;
}

// ---------------- prep: transposed fp16 weights ----------------
__global__ void convert_w_kernel(const float* __restrict__ W1, const float* __restrict__ W2) {
    int idx = blockIdx.x * blockDim.x + threadIdx.x;
    if (idx < 2 * 128 * 128) {
        int h = idx >> 14;
        int rem = idx & 16383;
        int n = rem >> 7;
        int k = rem & 127;
        g_W1t[idx] = __float2half_rn(W1[(size_t)(h * 128 + k) * 128 + n]);
    } else if (idx < 2 * 128 * 128 + 128 * 256) {
        int j = idx - 2 * 128 * 128;
        int n = j >> 8;
        int k = j & 255;
        g_W2t[j] = __float2half_rn(W2[(size_t)k * 128 + n]);
    }
}

// ---------------- aggh = fp16(agg); agg = 0 ----------------
__global__ void aggconv_kernel() {
    int i = blockIdx.x * blockDim.x + threadIdx.x;   // one per 4 elements
    if (i >= NN * DD / 4) return;
    float4 v = reinterpret_cast<float4*>(g_agg)[i];
    __half2 h0 = __floats2half2_rn(v.x, v.y);
    __half2 h1 = __floats2half2_rn(v.z, v.w);
    uint2 o;
    o.x = *reinterpret_cast<uint32_t*>(&h0);
    o.y = *reinterpret_cast<uint32_t*>(&h1);
    reinterpret_cast<uint2*>(g_aggh)[i] = o;
    reinterpret_cast<float4*>(g_agg)[i] = make_float4(0.f, 0.f, 0.f, 0.f);
}

// =======================================================================
// fp16 GEMM core: C(128x128) = A(128xK) @ Bt(128n x K)^T, BK=32, 3-stage cp.async.
// 256 threads = 8 warps (4m x 2n); warp tile 32x64.
// =======================================================================

struct Frag { float acc[2][8][4]; };

__device__ __forceinline__ void gemm_compute_step(const uint32_t* As, const uint32_t* Bs,
                                                  int wm, int wn, int lane, Frag& F) {
    const int g = lane >> 2;
    const int t = lane & 3;
#pragma unroll
    for (int kg = 0; kg < 2; kg++) {
        const int kb = kg * 8;   // word offset of this k16 slice
        uint32_t a[2][4];
#pragma unroll
        for (int mt = 0; mt < 2; mt++) {
            int row = wm * 32 + mt * 16 + g;
            a[mt][0] = As[row * RS + kb + t];
            a[mt][1] = As[(row + 8) * RS + kb + t];
            a[mt][2] = As[row * RS + kb + t + 4];
            a[mt][3] = As[(row + 8) * RS + kb + t + 4];
        }
#pragma unroll
        for (int nt = 0; nt < 8; nt++) {
            int n = wn * 64 + nt * 8 + g;
            uint32_t b[2];
            b[0] = Bs[n * RS + kb + t];
            b[1] = Bs[n * RS + kb + t + 4];
            mma_f16(F.acc[0][nt], a[0], b);
            mma_f16(F.acc[1][nt], a[1], b);
        }
    }
}

// Issue one BK=32 stage: A rows m0..m0+127, cols ka..ka+31 (fp16, row stride 128);
// B rows n=0..127 of Bt, cols kb..kb+31 (fp16, row stride krow).
__device__ __forceinline__ void gemm_issue_stage(uint32_t stage,
                                                 const __half* __restrict__ Ah, int m0, int ka,
                                                 const __half* __restrict__ Bt, int kb, int krow,
                                                 int tid) {
#pragma unroll
    for (int p = 0; p < 2; p++) {
        int id = tid + p * 256;
        int r  = id >> 2;          // 0..127
        int kc = id & 3;           // 16B chunk (8 fp16)
        int gr = m0 + r;
        int ok = (gr < NN) ? 16 : 0;
        int grc = (gr < NN) ? gr : (NN - 1);
        cp16(stage + (r * RS + kc * 4) * 4, Ah + (size_t)grc * 128 + ka + kc * 8, ok);
    }
#pragma unroll
    for (int p = 0; p < 2; p++) {
        int id = tid + p * 256;
        int n  = id >> 2;
        int kc = id & 3;
        cp16(stage + (A_STAGE_WORDS + n * RS + kc * 4) * 4,
             Bt + (size_t)n * krow + kb + kc * 8, 16);
    }
    cp_commit();
}

// ---------------- GEMM 1: Yh[:, half*128:+128] = fp16(Xh @ W1half) ----------------
__global__ void __launch_bounds__(256, 2) proj_kernel() {
    extern __shared__ float sm[];
    const uint32_t smem_base = (uint32_t)__cvta_generic_to_shared(sm);

    const int half = blockIdx.y;
    const __half* Bt = g_W1t + half * (128 * 128);
    const int m0 = blockIdx.x * 128;

    const int tid  = threadIdx.x;
    const int lane = tid & 31;
    const int wid  = tid >> 5;
    const int wm   = wid & 3;
    const int wn   = wid >> 2;

    Frag F;
#pragma unroll
    for (int mt = 0; mt < 2; mt++)
#pragma unroll
        for (int nt = 0; nt < 8; nt++)
#pragma unroll
            for (int j = 0; j < 4; j++) F.acc[mt][nt][j] = 0.f;

    const int NS = 4;  // K=128 / 32
    gemm_issue_stage(smem_base + 0 * STAGE_WORDS * 4, g_Xh, m0, 0,  Bt, 0,  128, tid);
    gemm_issue_stage(smem_base + 1 * STAGE_WORDS * 4, g_Xh, m0, 32, Bt, 32, 128, tid);

#pragma unroll
    for (int s = 0; s < NS; s++) {
        // Guarantee stage s landed: on the last step the newest commit IS stage s,
        // so we must drain fully (wait<0>); otherwise wait<1> suffices.
        if (s + 1 < NS) cp_wait<1>(); else cp_wait<0>();
        __syncthreads();
        int nxt = s + 2;
        if (nxt < NS)
            gemm_issue_stage(smem_base + (nxt % NSTAGE) * STAGE_WORDS * 4,
                             g_Xh, m0, nxt * 32, Bt, nxt * 32, 128, tid);
        const uint32_t* stage = (const uint32_t*)sm + (s % NSTAGE) * STAGE_WORDS;
        gemm_compute_step(stage, stage + A_STAGE_WORDS, wm, wn, lane, F);
    }

    // Epilogue: write fp16 Y
    const int g = lane >> 2;
    const int t = lane & 3;
#pragma unroll
    for (int mt = 0; mt < 2; mt++) {
        int row0 = m0 + wm * 32 + mt * 16 + g;
#pragma unroll
        for (int nt = 0; nt < 8; nt++) {
            int col = wn * 64 + nt * 8 + 2 * t;
            if (row0 < NN) {
                __half2 v = __floats2half2_rn(F.acc[mt][nt][0], F.acc[mt][nt][1]);
                *reinterpret_cast<__half2*>(g_Yh + (size_t)row0 * 256 + half * 128 + col) = v;
            }
            if (row0 + 8 < NN) {
                __half2 v = __floats2half2_rn(F.acc[mt][nt][2], F.acc[mt][nt][3]);
                *reinterpret_cast<__half2*>(g_Yh + (size_t)(row0 + 8) * 256 + half * 128 + col) = v;
            }
        }
    }
}

// ---------------- Edge pass: agg[dst] += relu(Ya[src] + Yb[dst] + b1) ----------------
__global__ void __launch_bounds__(256) edge_kernel(const int* __restrict__ esrc,
                                                   const int* __restrict__ edst,
                                                   const float* __restrict__ b1) {
    int e = blockIdx.x * 8 + (threadIdx.x >> 5);
    if (e >= NE) return;
    int lane = threadIdx.x & 31;
    int s = __ldg(esrc + e);
    int d = __ldg(edst + e);

    uint2 ua = *(reinterpret_cast<const uint2*>(g_Yh + (size_t)s * 256) + lane);
    uint2 ub = *(reinterpret_cast<const uint2*>(g_Yh + (size_t)d * 256 + 128) + lane);
    float4 bb = reinterpret_cast<const float4*>(b1)[lane];

    float2 a01 = __half22float2(*reinterpret_cast<__half2*>(&ua.x));
    float2 a23 = __half22float2(*reinterpret_cast<__half2*>(&ua.y));
    float2 b01 = __half22float2(*reinterpret_cast<__half2*>(&ub.x));
    float2 b23 = __half22float2(*reinterpret_cast<__half2*>(&ub.y));

    float m0 = fmaxf(a01.x + b01.x + bb.x, 0.f);
    float m1 = fmaxf(a01.y + b01.y + bb.y, 0.f);
    float m2 = fmaxf(a23.x + b23.x + bb.z, 0.f);
    float m3 = fmaxf(a23.y + b23.y + bb.w, 0.f);

    float* p = g_agg + (size_t)d * DD + lane * 4;
    asm volatile("red.global.add.v4.f32 [%0], {%1, %2, %3, %4};"
                 :: "l"(p), "f"(m0), "f"(m1), "f"(m2), "f"(m3) : "memory");
}

// ---------------- GEMM 2 + epilogue: out = x + relu([Xh|aggh] @ W2 + b2) ----------------
__global__ void __launch_bounds__(256, 2) update_kernel(const float* __restrict__ X,
                                                        const float* __restrict__ b2,
                                                        float* __restrict__ out) {
    extern __shared__ float sm[];
    const uint32_t smem_base = (uint32_t)__cvta_generic_to_shared(sm);

    const int m0 = blockIdx.x * 128;

    const int tid  = threadIdx.x;
    const int lane = tid & 31;
    const int wid  = tid >> 5;
    const int wm   = wid & 3;
    const int wn   = wid >> 2;

    Frag F;
#pragma unroll
    for (int mt = 0; mt < 2; mt++)
#pragma unroll
        for (int nt = 0; nt < 8; nt++)
#pragma unroll
            for (int j = 0; j < 4; j++) F.acc[mt][nt][j] = 0.f;

    const int NS = 8;  // K=256 / 32
    gemm_issue_stage(smem_base + 0 * STAGE_WORDS * 4, g_Xh, m0, 0,  g_W2t, 0,  256, tid);
    gemm_issue_stage(smem_base + 1 * STAGE_WORDS * 4, g_Xh, m0, 32, g_W2t, 32, 256, tid);

#pragma unroll
    for (int s = 0; s < NS; s++) {
        if (s + 1 < NS) cp_wait<1>(); else cp_wait<0>();
        __syncthreads();
        int nxt = s + 2;
        if (nxt < NS) {
            const __half* Ah = (nxt < 4) ? g_Xh : g_aggh;
            gemm_issue_stage(smem_base + (nxt % NSTAGE) * STAGE_WORDS * 4,
                             Ah, m0, (nxt * 32) & 127, g_W2t, nxt * 32, 256, tid);
        }
        const uint32_t* stage = (const uint32_t*)sm + (s % NSTAGE) * STAGE_WORDS;
        gemm_compute_step(stage, stage + A_STAGE_WORDS, wm, wn, lane, F);
    }

    // Epilogue: out = x + relu(acc + b2)
    const int g = lane >> 2;
    const int t = lane & 3;
#pragma unroll
    for (int mt = 0; mt < 2; mt++) {
        int row0 = m0 + wm * 32 + mt * 16 + g;
#pragma unroll
        for (int nt = 0; nt < 8; nt++) {
            int col = wn * 64 + nt * 8 + 2 * t;
            float2 bb = *reinterpret_cast<const float2*>(b2 + col);
            if (row0 < NN) {
                float2 x0 = *reinterpret_cast<const float2*>(X + (size_t)row0 * 128 + col);
                float2 v;
                v.x = x0.x + fmaxf(F.acc[mt][nt][0] + bb.x, 0.f);
                v.y = x0.y + fmaxf(F.acc[mt][nt][1] + bb.y, 0.f);
                *reinterpret_cast<float2*>(out + (size_t)row0 * 128 + col) = v;
            }
            if (row0 + 8 < NN) {
                float2 x1 = *reinterpret_cast<const float2*>(X + (size_t)(row0 + 8) * 128 + col);
                float2 v;
                v.x = x1.x + fmaxf(F.acc[mt][nt][2] + bb.x, 0.f);
                v.y = x1.y + fmaxf(F.acc[mt][nt][3] + bb.y, 0.f);
                *reinterpret_cast<float2*>(out + (size_t)(row0 + 8) * 128 + col) = v;
            }
        }
    }
}

extern "C" void kernel_launch(void* const* d_in, const int* in_sizes, int n_in,
                              void* d_out, int out_size) {
    const float* x    = (const float*)d_in[0];
    const int*   esrc = (const int*)d_in[1];
    const int*   edst = (const int*)d_in[2];
    const float* W1   = (const float*)d_in[3];
    const float* b1   = (const float*)d_in[4];
    const float* W2   = (const float*)d_in[5];
    const float* b2   = (const float*)d_in[6];
    float*       out  = (float*)d_out;

    (void)in_sizes; (void)n_in; (void)out_size;

    cudaFuncSetAttribute(proj_kernel,   cudaFuncAttributeMaxDynamicSharedMemorySize, SMEM_BYTES);
    cudaFuncSetAttribute(update_kernel, cudaFuncAttributeMaxDynamicSharedMemorySize, SMEM_BYTES);

    // 0. fp16 operand prep
    convert_x_kernel<<<(NN * DD / 8 + 255) / 256, 256>>>(x);
    convert_w_kernel<<<(2 * 128 * 128 + 128 * 256 + 255) / 256, 256>>>(W1, W2);
    // 1. Yh = fp16(Xh @ [W1a | W1b])   (factored edge MLP, fp16 MMA)
    dim3 gProj((NN + 127) / 128, 2);
    proj_kernel<<<gProj, 256, SMEM_BYTES>>>();
    // 2. per-edge: agg[dst] += relu(Ya[src] + Yb[dst] + b1)   (agg==0 on entry)
    edge_kernel<<<(NE + 7) / 8, 256>>>(esrc, edst, b1);
    // 3. aggh = fp16(agg); agg = 0
    aggconv_kernel<<<(NN * DD / 4 + 255) / 256, 256>>>();
    // 4. out = x + relu([Xh|aggh] @ W2 + b2)   (fp16 MMA)
    update_kernel<<<(NN + 127) / 128, 256, SMEM_BYTES>>>(x, b2, out);
}

// round 11
// speedup vs baseline: 1.8154x; 1.8154x over previous
#include <cuda_runtime.h>
#include <cuda_fp16.h>
#include <cstdint>

#define NN 50000
#define NE 600000
#define DD 128

// Scratch (device globals — zero-initialized at module load; aggconv_kernel
// re-zeros g_agg every launch, so agg==0 at every kernel_launch entry).
// g_Yh doubles as storage for aggh: after the edge pass Yh is dead, and
// aggconv writes fp16(agg) into its first NN*128 halves. This keeps the
// L2 working set small enough that the edge pass stays L2-resident.
static __device__ __half g_Yh[(size_t)NN * 256];   // fp16 proj: 0:128 = x@W1a, 128:256 = x@W1b; later aliased as aggh[N][128]
static __device__ float  g_agg[(size_t)NN * DD];   // fp32 segment sums (atomics)
static __device__ __half g_Xh[(size_t)NN * DD];    // fp16 copy of X
static __device__ __half g_W1t[2 * 128 * 128];     // [half][n][k] fp16 (transposed W1)
static __device__ __half g_W2t[128 * 256];         // [n][k] fp16 (transposed W2)

// ---------------- helpers ----------------
__device__ __forceinline__ void mma_f16(float* d, const uint32_t* a, const uint32_t* b) {
    asm volatile(
        "mma.sync.aligned.m16n8k16.row.col.f32.f16.f16.f32 "
        "{%0,%1,%2,%3}, {%4,%5,%6,%7}, {%8,%9}, {%0,%1,%2,%3};"
        : "+f"(d[0]), "+f"(d[1]), "+f"(d[2]), "+f"(d[3])
        : "r"(a[0]), "r"(a[1]), "r"(a[2]), "r"(a[3]), "r"(b[0]), "r"(b[1]));
}

__device__ __forceinline__ void cp16(uint32_t dst_smem, const void* src, int src_bytes) {
    asm volatile("cp.async.cg.shared.global [%0], [%1], 16, %2;"
                 :: "r"(dst_smem), "l"(src), "r"(src_bytes));
}
__device__ __forceinline__ void cp_commit() { asm volatile("cp.async.commit_group;"); }
template <int N>
__device__ __forceinline__ void cp_wait() { asm volatile("cp.async.wait_group %0;" :: "n"(N)); }

// SMEM layout (fp16, BK=32): row = 32 fp16 + 8 pad = 40 fp16 = 20 words (80B).
#define RS 20                                   // words per row
#define A_STAGE_WORDS (128 * RS)                // 2560
#define B_STAGE_WORDS (128 * RS)                // 2560
#define STAGE_WORDS (A_STAGE_WORDS + B_STAGE_WORDS)  // 5120
#define NSTAGE 3
#define SMEM_BYTES (NSTAGE * STAGE_WORDS * 4)   // 61440

// ---------------- prep: Xh = fp16(X) ----------------
__global__ void convert_x_kernel(const float* __restrict__ X) {
    int i = blockIdx.x * blockDim.x + threadIdx.x;   // one per 8 elements
    if (i >= NN * DD / 8) return;
    const float4* src = reinterpret_cast<const float4*>(X) + i * 2;
    float4 v0 = src[0], v1 = src[1];
    __half2 h0 = __floats2half2_rn(v0.x, v0.y);
    __half2 h1 = __floats2half2_rn(v0.z, v0.w);
    __half2 h2 = __floats2half2_rn(v1.x, v1.y);
    __half2 h3 = __floats2half2_rn(v1.z, v1.w);
    uint4 o;
    o.x = *reinterpret_cast<uint32_t*>(&h0);
    o.y = *reinterpret_cast<uint32_t*>(&h1);
    o.z = *reinterpret_cast<uint32_t*>(&h2);
    o.w = *reinterpret_cast<uint32_t*>(&h3);
    reinterpret_cast<uint4*>(g_Xh)[i] = o;
}

// ---------------- prep: transposed fp16 weights ----------------
__global__ void convert_w_kernel(const float* __restrict__ W1, const float* __restrict__ W2) {
    int idx = blockIdx.x * blockDim.x + threadIdx.x;
    if (idx < 2 * 128 * 128) {
        int h = idx >> 14;
        int rem = idx & 16383;
        int n = rem >> 7;
        int k = rem & 127;
        g_W1t[idx] = __float2half_rn(W1[(size_t)(h * 128 + k) * 128 + n]);
    } else if (idx < 2 * 128 * 128 + 128 * 256) {
        int j = idx - 2 * 128 * 128;
        int n = j >> 8;
        int k = j & 255;
        g_W2t[j] = __float2half_rn(W2[(size_t)k * 128 + n]);
    }
}

// ---------------- aggh (aliased into g_Yh) = fp16(agg); agg = 0 ----------------
__global__ void aggconv_kernel() {
    int i = blockIdx.x * blockDim.x + threadIdx.x;   // one per 4 elements
    if (i >= NN * DD / 4) return;
    float4 v = reinterpret_cast<float4*>(g_agg)[i];
    __half2 h0 = __floats2half2_rn(v.x, v.y);
    __half2 h1 = __floats2half2_rn(v.z, v.w);
    uint2 o;
    o.x = *reinterpret_cast<uint32_t*>(&h0);
    o.y = *reinterpret_cast<uint32_t*>(&h1);
    reinterpret_cast<uint2*>(g_Yh)[i] = o;   // aggh lives in Yh's storage (Yh is dead now)
    reinterpret_cast<float4*>(g_agg)[i] = make_float4(0.f, 0.f, 0.f, 0.f);
}

// =======================================================================
// fp16 GEMM core: C(128x128) = A(128xK) @ Bt(128n x K)^T, BK=32, 3-stage cp.async.
// 256 threads = 8 warps (4m x 2n); warp tile 32x64.
// =======================================================================

struct Frag { float acc[2][8][4]; };

__device__ __forceinline__ void gemm_compute_step(const uint32_t* As, const uint32_t* Bs,
                                                  int wm, int wn, int lane, Frag& F) {
    const int g = lane >> 2;
    const int t = lane & 3;
#pragma unroll
    for (int kg = 0; kg < 2; kg++) {
        const int kb = kg * 8;   // word offset of this k16 slice
        uint32_t a[2][4];
#pragma unroll
        for (int mt = 0; mt < 2; mt++) {
            int row = wm * 32 + mt * 16 + g;
            a[mt][0] = As[row * RS + kb + t];
            a[mt][1] = As[(row + 8) * RS + kb + t];
            a[mt][2] = As[row * RS + kb + t + 4];
            a[mt][3] = As[(row + 8) * RS + kb + t + 4];
        }
#pragma unroll
        for (int nt = 0; nt < 8; nt++) {
            int n = wn * 64 + nt * 8 + g;
            uint32_t b[2];
            b[0] = Bs[n * RS + kb + t];
            b[1] = Bs[n * RS + kb + t + 4];
            mma_f16(F.acc[0][nt], a[0], b);
            mma_f16(F.acc[1][nt], a[1], b);
        }
    }
}

// Issue one BK=32 stage: A rows m0..m0+127, cols ka..ka+31 (fp16, row stride 128);
// B rows n=0..127 of Bt, cols kb..kb+31 (fp16, row stride krow).
__device__ __forceinline__ void gemm_issue_stage(uint32_t stage,
                                                 const __half* __restrict__ Ah, int m0, int ka,
                                                 const __half* __restrict__ Bt, int kb, int krow,
                                                 int tid) {
#pragma unroll
    for (int p = 0; p < 2; p++) {
        int id = tid + p * 256;
        int r  = id >> 2;          // 0..127
        int kc = id & 3;           // 16B chunk (8 fp16)
        int gr = m0 + r;
        int ok = (gr < NN) ? 16 : 0;
        int grc = (gr < NN) ? gr : (NN - 1);
        cp16(stage + (r * RS + kc * 4) * 4, Ah + (size_t)grc * 128 + ka + kc * 8, ok);
    }
#pragma unroll
    for (int p = 0; p < 2; p++) {
        int id = tid + p * 256;
        int n  = id >> 2;
        int kc = id & 3;
        cp16(stage + (A_STAGE_WORDS + n * RS + kc * 4) * 4,
             Bt + (size_t)n * krow + kb + kc * 8, 16);
    }
    cp_commit();
}

// ---------------- GEMM 1: Yh[:, half*128:+128] = fp16(Xh @ W1half) ----------------
__global__ void __launch_bounds__(256, 2) proj_kernel() {
    extern __shared__ float sm[];
    const uint32_t smem_base = (uint32_t)__cvta_generic_to_shared(sm);

    const int half = blockIdx.y;
    const __half* Bt = g_W1t + half * (128 * 128);
    const int m0 = blockIdx.x * 128;

    const int tid  = threadIdx.x;
    const int lane = tid & 31;
    const int wid  = tid >> 5;
    const int wm   = wid & 3;
    const int wn   = wid >> 2;

    Frag F;
#pragma unroll
    for (int mt = 0; mt < 2; mt++)
#pragma unroll
        for (int nt = 0; nt < 8; nt++)
#pragma unroll
            for (int j = 0; j < 4; j++) F.acc[mt][nt][j] = 0.f;

    const int NS = 4;  // K=128 / 32
    gemm_issue_stage(smem_base + 0 * STAGE_WORDS * 4, g_Xh, m0, 0,  Bt, 0,  128, tid);
    gemm_issue_stage(smem_base + 1 * STAGE_WORDS * 4, g_Xh, m0, 32, Bt, 32, 128, tid);

#pragma unroll
    for (int s = 0; s < NS; s++) {
        // Guarantee stage s landed: on the last step the newest commit IS stage s.
        if (s + 1 < NS) cp_wait<1>(); else cp_wait<0>();
        __syncthreads();
        int nxt = s + 2;
        if (nxt < NS)
            gemm_issue_stage(smem_base + (nxt % NSTAGE) * STAGE_WORDS * 4,
                             g_Xh, m0, nxt * 32, Bt, nxt * 32, 128, tid);
        const uint32_t* stage = (const uint32_t*)sm + (s % NSTAGE) * STAGE_WORDS;
        gemm_compute_step(stage, stage + A_STAGE_WORDS, wm, wn, lane, F);
    }

    // Epilogue: write fp16 Y
    const int g = lane >> 2;
    const int t = lane & 3;
#pragma unroll
    for (int mt = 0; mt < 2; mt++) {
        int row0 = m0 + wm * 32 + mt * 16 + g;
#pragma unroll
        for (int nt = 0; nt < 8; nt++) {
            int col = wn * 64 + nt * 8 + 2 * t;
            if (row0 < NN) {
                __half2 v = __floats2half2_rn(F.acc[mt][nt][0], F.acc[mt][nt][1]);
                *reinterpret_cast<__half2*>(g_Yh + (size_t)row0 * 256 + half * 128 + col) = v;
            }
            if (row0 + 8 < NN) {
                __half2 v = __floats2half2_rn(F.acc[mt][nt][2], F.acc[mt][nt][3]);
                *reinterpret_cast<__half2*>(g_Yh + (size_t)(row0 + 8) * 256 + half * 128 + col) = v;
            }
        }
    }
}

// ---------------- Edge pass: agg[dst] += relu(Ya[src] + Yb[dst] + b1) ----------------
// One warp handles 4 edges; b1 hoisted into registers (amortized).
#define EDGES_PER_WARP 4
__global__ void __launch_bounds__(256) edge_kernel(const int* __restrict__ esrc,
                                                   const int* __restrict__ edst,
                                                   const float* __restrict__ b1) {
    int warp = blockIdx.x * 8 + (threadIdx.x >> 5);
    int lane = threadIdx.x & 31;
    float4 bb = reinterpret_cast<const float4*>(b1)[lane];

    int e0 = warp * EDGES_PER_WARP;
#pragma unroll
    for (int j = 0; j < EDGES_PER_WARP; j++) {
        int e = e0 + j;
        if (e >= NE) return;
        int s = __ldg(esrc + e);
        int d = __ldg(edst + e);

        uint2 ua = *(reinterpret_cast<const uint2*>(g_Yh + (size_t)s * 256) + lane);
        uint2 ub = *(reinterpret_cast<const uint2*>(g_Yh + (size_t)d * 256 + 128) + lane);

        float2 a01 = __half22float2(*reinterpret_cast<__half2*>(&ua.x));
        float2 a23 = __half22float2(*reinterpret_cast<__half2*>(&ua.y));
        float2 b01 = __half22float2(*reinterpret_cast<__half2*>(&ub.x));
        float2 b23 = __half22float2(*reinterpret_cast<__half2*>(&ub.y));

        float m0 = fmaxf(a01.x + b01.x + bb.x, 0.f);
        float m1 = fmaxf(a01.y + b01.y + bb.y, 0.f);
        float m2 = fmaxf(a23.x + b23.x + bb.z, 0.f);
        float m3 = fmaxf(a23.y + b23.y + bb.w, 0.f);

        float* p = g_agg + (size_t)d * DD + lane * 4;
        asm volatile("red.global.add.v4.f32 [%0], {%1, %2, %3, %4};"
                     :: "l"(p), "f"(m0), "f"(m1), "f"(m2), "f"(m3) : "memory");
    }
}

// ---------------- GEMM 2 + epilogue: out = x + relu([Xh|aggh] @ W2 + b2) ----------------
__global__ void __launch_bounds__(256, 2) update_kernel(const float* __restrict__ X,
                                                        const float* __restrict__ b2,
                                                        float* __restrict__ out) {
    extern __shared__ float sm[];
    const uint32_t smem_base = (uint32_t)__cvta_generic_to_shared(sm);

    const int m0 = blockIdx.x * 128;

    const int tid  = threadIdx.x;
    const int lane = tid & 31;
    const int wid  = tid >> 5;
    const int wm   = wid & 3;
    const int wn   = wid >> 2;

    Frag F;
#pragma unroll
    for (int mt = 0; mt < 2; mt++)
#pragma unroll
        for (int nt = 0; nt < 8; nt++)
#pragma unroll
            for (int j = 0; j < 4; j++) F.acc[mt][nt][j] = 0.f;

    const __half* aggh = g_Yh;   // aggh aliased into Yh storage (written by aggconv)
    const int NS = 8;  // K=256 / 32
    gemm_issue_stage(smem_base + 0 * STAGE_WORDS * 4, g_Xh, m0, 0,  g_W2t, 0,  256, tid);
    gemm_issue_stage(smem_base + 1 * STAGE_WORDS * 4, g_Xh, m0, 32, g_W2t, 32, 256, tid);

#pragma unroll
    for (int s = 0; s < NS; s++) {
        if (s + 1 < NS) cp_wait<1>(); else cp_wait<0>();
        __syncthreads();
        int nxt = s + 2;
        if (nxt < NS) {
            const __half* Ah = (nxt < 4) ? g_Xh : aggh;
            gemm_issue_stage(smem_base + (nxt % NSTAGE) * STAGE_WORDS * 4,
                             Ah, m0, (nxt * 32) & 127, g_W2t, nxt * 32, 256, tid);
        }
        const uint32_t* stage = (const uint32_t*)sm + (s % NSTAGE) * STAGE_WORDS;
        gemm_compute_step(stage, stage + A_STAGE_WORDS, wm, wn, lane, F);
    }

    // Epilogue: out = x + relu(acc + b2)
    const int g = lane >> 2;
    const int t = lane & 3;
#pragma unroll
    for (int mt = 0; mt < 2; mt++) {
        int row0 = m0 + wm * 32 + mt * 16 + g;
#pragma unroll
        for (int nt = 0; nt < 8; nt++) {
            int col = wn * 64 + nt * 8 + 2 * t;
            float2 bb = *reinterpret_cast<const float2*>(b2 + col);
            if (row0 < NN) {
                float2 x0 = *reinterpret_cast<const float2*>(X + (size_t)row0 * 128 + col);
                float2 v;
                v.x = x0.x + fmaxf(F.acc[mt][nt][0] + bb.x, 0.f);
                v.y = x0.y + fmaxf(F.acc[mt][nt][1] + bb.y, 0.f);
                *reinterpret_cast<float2*>(out + (size_t)row0 * 128 + col) = v;
            }
            if (row0 + 8 < NN) {
                float2 x1 = *reinterpret_cast<const float2*>(X + (size_t)(row0 + 8) * 128 + col);
                float2 v;
                v.x = x1.x + fmaxf(F.acc[mt][nt][2] + bb.x, 0.f);
                v.y = x1.y + fmaxf(F.acc[mt][nt][3] + bb.y, 0.f);
                *reinterpret_cast<float2*>(out + (size_t)(row0 + 8) * 128 + col) = v;
            }
        }
    }
}

extern "C" void kernel_launch(void* const* d_in, const int* in_sizes, int n_in,
                              void* d_out, int out_size) {
    const float* x    = (const float*)d_in[0];
    const int*   esrc = (const int*)d_in[1];
    const int*   edst = (const int*)d_in[2];
    const float* W1   = (const float*)d_in[3];
    const float* b1   = (const float*)d_in[4];
    const float* W2   = (const float*)d_in[5];
    const float* b2   = (const float*)d_in[6];
    float*       out  = (float*)d_out;

    (void)in_sizes; (void)n_in; (void)out_size;

    cudaFuncSetAttribute(proj_kernel,   cudaFuncAttributeMaxDynamicSharedMemorySize, SMEM_BYTES);
    cudaFuncSetAttribute(update_kernel, cudaFuncAttributeMaxDynamicSharedMemorySize, SMEM_BYTES);

    // 0. fp16 operand prep
    convert_x_kernel<<<(NN * DD / 8 + 255) / 256, 256>>>(x);
    convert_w_kernel<<<(2 * 128 * 128 + 128 * 256 + 255) / 256, 256>>>(W1, W2);
    // 1. Yh = fp16(Xh @ [W1a | W1b])   (factored edge MLP, fp16 MMA)
    dim3 gProj((NN + 127) / 128, 2);
    proj_kernel<<<gProj, 256, SMEM_BYTES>>>();
    // 2. per-edge: agg[dst] += relu(Ya[src] + Yb[dst] + b1)   (agg==0 on entry)
    edge_kernel<<<NE / (8 * EDGES_PER_WARP), 256>>>(esrc, edst, b1);
    // 3. aggh (in Yh storage) = fp16(agg); agg = 0
    aggconv_kernel<<<(NN * DD / 4 + 255) / 256, 256>>>();
    // 4. out = x + relu([Xh|aggh] @ W2 + b2)   (fp16 MMA)
    update_kernel<<<(NN + 127) / 128, 256, SMEM_BYTES>>>(x, b2, out);
}

// round 12
// speedup vs baseline: 2.2013x; 1.2126x over previous
#include <cuda_runtime.h>
#include <cuda_fp16.h>
#include <cstdint>

#define NN 50000
#define NE 600000
#define DD 128
#define NBLK ((NN + 255) / 256)   // 196 scan blocks

// Scratch (device globals). g_cnt is re-zeroed every launch by convert_w_kernel;
// everything else is overwritten before being read each launch.
static __device__ __half g_Yh[(size_t)NN * 256];   // fp16 proj: 0:128 = x@W1a, 128:256 = x@W1b
static __device__ __half g_aggh[(size_t)NN * DD];  // fp16 aggregated messages
static __device__ __half g_Xh[(size_t)NN * DD];    // fp16 copy of X
static __device__ __half g_W1t[2 * 128 * 128];     // [half][n][k] fp16 (transposed W1)
static __device__ __half g_W2t[128 * 256];         // [n][k] fp16 (transposed W2)
static __device__ int    g_cnt[NN];                // per-dst degree (histogram)
static __device__ int    g_off[NN];                // exclusive prefix of g_cnt
static __device__ int    g_cur[NN];                // scatter cursor
static __device__ int    g_srt[NE];                // src indices grouped by dst
static __device__ int    g_bsum[NBLK];
static __device__ int    g_boff[NBLK];

// ---------------- helpers ----------------
__device__ __forceinline__ void mma_f16(float* d, const uint32_t* a, const uint32_t* b) {
    asm volatile(
        "mma.sync.aligned.m16n8k16.row.col.f32.f16.f16.f32 "
        "{%0,%1,%2,%3}, {%4,%5,%6,%7}, {%8,%9}, {%0,%1,%2,%3};"
        : "+f"(d[0]), "+f"(d[1]), "+f"(d[2]), "+f"(d[3])
        : "r"(a[0]), "r"(a[1]), "r"(a[2]), "r"(a[3]), "r"(b[0]), "r"(b[1]));
}

__device__ __forceinline__ void cp16(uint32_t dst_smem, const void* src, int src_bytes) {
    asm volatile("cp.async.cg.shared.global [%0], [%1], 16, %2;"
                 :: "r"(dst_smem), "l"(src), "r"(src_bytes));
}
__device__ __forceinline__ void cp_commit() { asm volatile("cp.async.commit_group;"); }
template <int N>
__device__ __forceinline__ void cp_wait() { asm volatile("cp.async.wait_group %0;" :: "n"(N)); }

// SMEM layout (fp16, BK=32): row = 32 fp16 + 8 pad = 40 fp16 = 20 words (80B).
#define RS 20
#define A_STAGE_WORDS (128 * RS)
#define B_STAGE_WORDS (128 * RS)
#define STAGE_WORDS (A_STAGE_WORDS + B_STAGE_WORDS)
#define NSTAGE 3
#define SMEM_BYTES (NSTAGE * STAGE_WORDS * 4)   // 61440

// ---------------- prep: Xh = fp16(X) ----------------
__global__ void convert_x_kernel(const float* __restrict__ X) {
    int i = blockIdx.x * blockDim.x + threadIdx.x;
    if (i >= NN * DD / 8) return;
    const float4* src = reinterpret_cast<const float4*>(X) + i * 2;
    float4 v0 = src[0], v1 = src[1];
    __half2 h0 = __floats2half2_rn(v0.x, v0.y);
    __half2 h1 = __floats2half2_rn(v0.z, v0.w);
    __half2 h2 = __floats2half2_rn(v1.x, v1.y);
    __half2 h3 = __floats2half2_rn(v1.z, v1.w);
    uint4 o;
    o.x = *reinterpret_cast<uint32_t*>(&h0);
    o.y = *reinterpret_cast<uint32_t*>(&h1);
    o.z = *reinterpret_cast<uint32_t*>(&h2);
    o.w = *reinterpret_cast<uint32_t*>(&h3);
    reinterpret_cast<uint4*>(g_Xh)[i] = o;
}

// ---------------- prep: transposed fp16 weights; also zero histogram ----------------
__global__ void convert_w_kernel(const float* __restrict__ W1, const float* __restrict__ W2) {
    int idx = blockIdx.x * blockDim.x + threadIdx.x;
    if (idx < NN) g_cnt[idx] = 0;
    if (idx < 2 * 128 * 128) {
        int h = idx >> 14;
        int rem = idx & 16383;
        int n = rem >> 7;
        int k = rem & 127;
        g_W1t[idx] = __float2half_rn(W1[(size_t)(h * 128 + k) * 128 + n]);
    } else if (idx < 2 * 128 * 128 + 128 * 256) {
        int j = idx - 2 * 128 * 128;
        int n = j >> 8;
        int k = j & 255;
        g_W2t[j] = __float2half_rn(W2[(size_t)k * 128 + n]);
    }
}

// ---------------- counting sort of edges by dst ----------------
__global__ void hist_kernel(const int* __restrict__ edst) {
    int e = blockIdx.x * 256 + threadIdx.x;
    if (e < NE) atomicAdd(&g_cnt[__ldg(edst + e)], 1);
}

__global__ void scan1_kernel() {   // per-block sums of g_cnt
    __shared__ int sh[256];
    int i = blockIdx.x * 256 + threadIdx.x;
    int t = threadIdx.x;
    sh[t] = (i < NN) ? g_cnt[i] : 0;
    __syncthreads();
#pragma unroll
    for (int s = 128; s > 0; s >>= 1) {
        if (t < s) sh[t] += sh[t + s];
        __syncthreads();
    }
    if (t == 0) g_bsum[blockIdx.x] = sh[0];
}

__global__ void scan2_kernel() {   // 1 block: exclusive scan of block sums
    __shared__ int sh[256];
    int t = threadIdx.x;
    int v = (t < NBLK) ? g_bsum[t] : 0;
    sh[t] = v;
    __syncthreads();
#pragma unroll
    for (int d = 1; d < 256; d <<= 1) {
        int x = (t >= d) ? sh[t - d] : 0;
        __syncthreads();
        sh[t] += x;
        __syncthreads();
    }
    if (t < NBLK) g_boff[t] = sh[t] - v;
}

__global__ void scan3_kernel() {   // finalize: g_off / g_cur = global exclusive scan
    __shared__ int sh[256];
    int i = blockIdx.x * 256 + threadIdx.x;
    int t = threadIdx.x;
    int v = (i < NN) ? g_cnt[i] : 0;
    sh[t] = v;
    __syncthreads();
#pragma unroll
    for (int d = 1; d < 256; d <<= 1) {
        int x = (t >= d) ? sh[t - d] : 0;
        __syncthreads();
        sh[t] += x;
        __syncthreads();
    }
    if (i < NN) {
        int exc = sh[t] - v + g_boff[blockIdx.x];
        g_off[i] = exc;
        g_cur[i] = exc;
    }
}

__global__ void scatter_kernel(const int* __restrict__ esrc, const int* __restrict__ edst) {
    int e = blockIdx.x * 256 + threadIdx.x;
    if (e < NE) {
        int d = __ldg(edst + e);
        int pos = atomicAdd(&g_cur[d], 1);
        g_srt[pos] = __ldg(esrc + e);
    }
}

// =======================================================================
// fp16 GEMM core (unchanged from R10)
// =======================================================================

struct Frag { float acc[2][8][4]; };

__device__ __forceinline__ void gemm_compute_step(const uint32_t* As, const uint32_t* Bs,
                                                  int wm, int wn, int lane, Frag& F) {
    const int g = lane >> 2;
    const int t = lane & 3;
#pragma unroll
    for (int kg = 0; kg < 2; kg++) {
        const int kb = kg * 8;
        uint32_t a[2][4];
#pragma unroll
        for (int mt = 0; mt < 2; mt++) {
            int row = wm * 32 + mt * 16 + g;
            a[mt][0] = As[row * RS + kb + t];
            a[mt][1] = As[(row + 8) * RS + kb + t];
            a[mt][2] = As[row * RS + kb + t + 4];
            a[mt][3] = As[(row + 8) * RS + kb + t + 4];
        }
#pragma unroll
        for (int nt = 0; nt < 8; nt++) {
            int n = wn * 64 + nt * 8 + g;
            uint32_t b[2];
            b[0] = Bs[n * RS + kb + t];
            b[1] = Bs[n * RS + kb + t + 4];
            mma_f16(F.acc[0][nt], a[0], b);
            mma_f16(F.acc[1][nt], a[1], b);
        }
    }
}

__device__ __forceinline__ void gemm_issue_stage(uint32_t stage,
                                                 const __half* __restrict__ Ah, int m0, int ka,
                                                 const __half* __restrict__ Bt, int kb, int krow,
                                                 int tid) {
#pragma unroll
    for (int p = 0; p < 2; p++) {
        int id = tid + p * 256;
        int r  = id >> 2;
        int kc = id & 3;
        int gr = m0 + r;
        int ok = (gr < NN) ? 16 : 0;
        int grc = (gr < NN) ? gr : (NN - 1);
        cp16(stage + (r * RS + kc * 4) * 4, Ah + (size_t)grc * 128 + ka + kc * 8, ok);
    }
#pragma unroll
    for (int p = 0; p < 2; p++) {
        int id = tid + p * 256;
        int n  = id >> 2;
        int kc = id & 3;
        cp16(stage + (A_STAGE_WORDS + n * RS + kc * 4) * 4,
             Bt + (size_t)n * krow + kb + kc * 8, 16);
    }
    cp_commit();
}

// ---------------- GEMM 1: Yh[:, half*128:+128] = fp16(Xh @ W1half) ----------------
__global__ void __launch_bounds__(256, 2) proj_kernel() {
    extern __shared__ float sm[];
    const uint32_t smem_base = (uint32_t)__cvta_generic_to_shared(sm);

    const int half = blockIdx.y;
    const __half* Bt = g_W1t + half * (128 * 128);
    const int m0 = blockIdx.x * 128;

    const int tid  = threadIdx.x;
    const int lane = tid & 31;
    const int wid  = tid >> 5;
    const int wm   = wid & 3;
    const int wn   = wid >> 2;

    Frag F;
#pragma unroll
    for (int mt = 0; mt < 2; mt++)
#pragma unroll
        for (int nt = 0; nt < 8; nt++)
#pragma unroll
            for (int j = 0; j < 4; j++) F.acc[mt][nt][j] = 0.f;

    const int NS = 4;
    gemm_issue_stage(smem_base + 0 * STAGE_WORDS * 4, g_Xh, m0, 0,  Bt, 0,  128, tid);
    gemm_issue_stage(smem_base + 1 * STAGE_WORDS * 4, g_Xh, m0, 32, Bt, 32, 128, tid);

#pragma unroll
    for (int s = 0; s < NS; s++) {
        if (s + 1 < NS) cp_wait<1>(); else cp_wait<0>();
        __syncthreads();
        int nxt = s + 2;
        if (nxt < NS)
            gemm_issue_stage(smem_base + (nxt % NSTAGE) * STAGE_WORDS * 4,
                             g_Xh, m0, nxt * 32, Bt, nxt * 32, 128, tid);
        const uint32_t* stage = (const uint32_t*)sm + (s % NSTAGE) * STAGE_WORDS;
        gemm_compute_step(stage, stage + A_STAGE_WORDS, wm, wn, lane, F);
    }

    const int g = lane >> 2;
    const int t = lane & 3;
#pragma unroll
    for (int mt = 0; mt < 2; mt++) {
        int row0 = m0 + wm * 32 + mt * 16 + g;
#pragma unroll
        for (int nt = 0; nt < 8; nt++) {
            int col = wn * 64 + nt * 8 + 2 * t;
            if (row0 < NN) {
                __half2 v = __floats2half2_rn(F.acc[mt][nt][0], F.acc[mt][nt][1]);
                *reinterpret_cast<__half2*>(g_Yh + (size_t)row0 * 256 + half * 128 + col) = v;
            }
            if (row0 + 8 < NN) {
                __half2 v = __floats2half2_rn(F.acc[mt][nt][2], F.acc[mt][nt][3]);
                *reinterpret_cast<__half2*>(g_Yh + (size_t)(row0 + 8) * 256 + half * 128 + col) = v;
            }
        }
    }
}

// ---------------- Aggregate: one warp per dst node, fp32 register accumulation ----------------
// aggh[d] = fp16( sum_{s in srcs(d)} relu(Ya[s] + Yb[d] + b1) )
__global__ void __launch_bounds__(256) aggregate_kernel(const float* __restrict__ b1) {
    int d = blockIdx.x * 8 + (threadIdx.x >> 5);
    if (d >= NN) return;
    int lane = threadIdx.x & 31;

    int base = g_off[d];
    int deg  = g_cnt[d];

    float4 bb = reinterpret_cast<const float4*>(b1)[lane];
    uint2 ub = *(reinterpret_cast<const uint2*>(g_Yh + (size_t)d * 256 + 128) + lane);
    float2 b01 = __half22float2(*reinterpret_cast<__half2*>(&ub.x));
    float2 b23 = __half22float2(*reinterpret_cast<__half2*>(&ub.y));
    float c0 = b01.x + bb.x, c1 = b01.y + bb.y, c2 = b23.x + bb.z, c3 = b23.y + bb.w;

    float a0 = 0.f, a1 = 0.f, a2 = 0.f, a3 = 0.f;
#pragma unroll 2
    for (int i = 0; i < deg; i++) {
        int s = __ldg(g_srt + base + i);
        uint2 ua = *(reinterpret_cast<const uint2*>(g_Yh + (size_t)s * 256) + lane);
        float2 p01 = __half22float2(*reinterpret_cast<__half2*>(&ua.x));
        float2 p23 = __half22float2(*reinterpret_cast<__half2*>(&ua.y));
        a0 += fmaxf(p01.x + c0, 0.f);
        a1 += fmaxf(p01.y + c1, 0.f);
        a2 += fmaxf(p23.x + c2, 0.f);
        a3 += fmaxf(p23.y + c3, 0.f);
    }

    __half2 h0 = __floats2half2_rn(a0, a1);
    __half2 h1 = __floats2half2_rn(a2, a3);
    uint2 o;
    o.x = *reinterpret_cast<uint32_t*>(&h0);
    o.y = *reinterpret_cast<uint32_t*>(&h1);
    *(reinterpret_cast<uint2*>(g_aggh + (size_t)d * 128) + lane) = o;
}

// ---------------- GEMM 2 + epilogue: out = x + relu([Xh|aggh] @ W2 + b2) ----------------
__global__ void __launch_bounds__(256, 2) update_kernel(const float* __restrict__ X,
                                                        const float* __restrict__ b2,
                                                        float* __restrict__ out) {
    extern __shared__ float sm[];
    const uint32_t smem_base = (uint32_t)__cvta_generic_to_shared(sm);

    const int m0 = blockIdx.x * 128;

    const int tid  = threadIdx.x;
    const int lane = tid & 31;
    const int wid  = tid >> 5;
    const int wm   = wid & 3;
    const int wn   = wid >> 2;

    Frag F;
#pragma unroll
    for (int mt = 0; mt < 2; mt++)
#pragma unroll
        for (int nt = 0; nt < 8; nt++)
#pragma unroll
            for (int j = 0; j < 4; j++) F.acc[mt][nt][j] = 0.f;

    const int NS = 8;
    gemm_issue_stage(smem_base + 0 * STAGE_WORDS * 4, g_Xh, m0, 0,  g_W2t, 0,  256, tid);
    gemm_issue_stage(smem_base + 1 * STAGE_WORDS * 4, g_Xh, m0, 32, g_W2t, 32, 256, tid);

#pragma unroll
    for (int s = 0; s < NS; s++) {
        if (s + 1 < NS) cp_wait<1>(); else cp_wait<0>();
        __syncthreads();
        int nxt = s + 2;
        if (nxt < NS) {
            const __half* Ah = (nxt < 4) ? g_Xh : g_aggh;
            gemm_issue_stage(smem_base + (nxt % NSTAGE) * STAGE_WORDS * 4,
                             Ah, m0, (nxt * 32) & 127, g_W2t, nxt * 32, 256, tid);
        }
        const uint32_t* stage = (const uint32_t*)sm + (s % NSTAGE) * STAGE_WORDS;
        gemm_compute_step(stage, stage + A_STAGE_WORDS, wm, wn, lane, F);
    }

    const int g = lane >> 2;
    const int t = lane & 3;
#pragma unroll
    for (int mt = 0; mt < 2; mt++) {
        int row0 = m0 + wm * 32 + mt * 16 + g;
#pragma unroll
        for (int nt = 0; nt < 8; nt++) {
            int col = wn * 64 + nt * 8 + 2 * t;
            float2 bb = *reinterpret_cast<const float2*>(b2 + col);
            if (row0 < NN) {
                float2 x0 = *reinterpret_cast<const float2*>(X + (size_t)row0 * 128 + col);
                float2 v;
                v.x = x0.x + fmaxf(F.acc[mt][nt][0] + bb.x, 0.f);
                v.y = x0.y + fmaxf(F.acc[mt][nt][1] + bb.y, 0.f);
                *reinterpret_cast<float2*>(out + (size_t)row0 * 128 + col) = v;
            }
            if (row0 + 8 < NN) {
                float2 x1 = *reinterpret_cast<const float2*>(X + (size_t)(row0 + 8) * 128 + col);
                float2 v;
                v.x = x1.x + fmaxf(F.acc[mt][nt][2] + bb.x, 0.f);
                v.y = x1.y + fmaxf(F.acc[mt][nt][3] + bb.y, 0.f);
                *reinterpret_cast<float2*>(out + (size_t)(row0 + 8) * 128 + col) = v;
            }
        }
    }
}

extern "C" void kernel_launch(void* const* d_in, const int* in_sizes, int n_in,
                              void* d_out, int out_size) {
    const float* x    = (const float*)d_in[0];
    const int*   esrc = (const int*)d_in[1];
    const int*   edst = (const int*)d_in[2];
    const float* W1   = (const float*)d_in[3];
    const float* b1   = (const float*)d_in[4];
    const float* W2   = (const float*)d_in[5];
    const float* b2   = (const float*)d_in[6];
    float*       out  = (float*)d_out;

    (void)in_sizes; (void)n_in; (void)out_size;

    cudaFuncSetAttribute(proj_kernel,   cudaFuncAttributeMaxDynamicSharedMemorySize, SMEM_BYTES);
    cudaFuncSetAttribute(update_kernel, cudaFuncAttributeMaxDynamicSharedMemorySize, SMEM_BYTES);

    // 0. fp16 operand prep (+ zero histogram)
    convert_x_kernel<<<(NN * DD / 8 + 255) / 256, 256>>>(x);
    convert_w_kernel<<<(2 * 128 * 128 + 128 * 256 + 255) / 256, 256>>>(W1, W2);
    // 1. counting sort of edges by dst
    hist_kernel<<<(NE + 255) / 256, 256>>>(edst);
    scan1_kernel<<<NBLK, 256>>>();
    scan2_kernel<<<1, 256>>>();
    scan3_kernel<<<NBLK, 256>>>();
    scatter_kernel<<<(NE + 255) / 256, 256>>>(esrc, edst);
    // 2. Yh = fp16(Xh @ [W1a | W1b])
    dim3 gProj((NN + 127) / 128, 2);
    proj_kernel<<<gProj, 256, SMEM_BYTES>>>();
    // 3. gather-aggregate per dst node (fp32 regs), write aggh fp16
    aggregate_kernel<<<(NN * 32 + 255) / 256, 256>>>(b1);
    // 4. out = x + relu([Xh|aggh] @ W2 + b2)
    update_kernel<<<(NN + 127) / 128, 256, SMEM_BYTES>>>(x, b2, out);
}

// round 13
// speedup vs baseline: 2.3338x; 1.0602x over previous
#include <cuda_runtime.h>
#include <cuda_fp16.h>
#include <cstdint>

#define NN 50000
#define NE 600000
#define DD 128
#define NBLK ((NN + 255) / 256)   // 196 scan blocks

// Scratch (device globals). Invariants maintained across launches:
//  - g_cnt == 0 at entry (zero-init at load; scan_kernel re-zeros after reading)
//  - g_ticket == 0 at entry to scan (prep_kernel zeros it earlier in same launch)
static __device__ __half g_Yh[(size_t)NN * 256];   // fp16 proj: 0:128 = x@W1a, 128:256 = x@W1b
static __device__ __half g_aggh[(size_t)NN * DD];  // fp16 aggregated messages
static __device__ __half g_Xh[(size_t)NN * DD];    // fp16 copy of X
static __device__ __half g_W1t[2 * 128 * 128];     // [half][n][k] fp16 (transposed W1)
static __device__ __half g_W2t[128 * 256];         // [n][k] fp16 (transposed W2)
static __device__ int    g_cnt[NN];                // per-dst degree histogram (zeroed by scan)
static __device__ int    g_off[NN];                // group base offset per dst
static __device__ int    g_deg[NN];                // degree per dst (copied from cnt)
static __device__ int    g_cur[NN];                // scatter cursor
static __device__ int    g_srt[NE];                // src indices grouped by dst
static __device__ int    g_ticket;                 // atomic base allocator for scan

// ---------------- helpers ----------------
__device__ __forceinline__ void mma_f16(float* d, const uint32_t* a, const uint32_t* b) {
    asm volatile(
        "mma.sync.aligned.m16n8k16.row.col.f32.f16.f16.f32 "
        "{%0,%1,%2,%3}, {%4,%5,%6,%7}, {%8,%9}, {%0,%1,%2,%3};"
        : "+f"(d[0]), "+f"(d[1]), "+f"(d[2]), "+f"(d[3])
        : "r"(a[0]), "r"(a[1]), "r"(a[2]), "r"(a[3]), "r"(b[0]), "r"(b[1]));
}

__device__ __forceinline__ void cp16(uint32_t dst_smem, const void* src, int src_bytes) {
    asm volatile("cp.async.cg.shared.global [%0], [%1], 16, %2;"
                 :: "r"(dst_smem), "l"(src), "r"(src_bytes));
}
__device__ __forceinline__ void cp_commit() { asm volatile("cp.async.commit_group;"); }
template <int N>
__device__ __forceinline__ void cp_wait() { asm volatile("cp.async.wait_group %0;" :: "n"(N)); }

// SMEM layout (fp16, BK=32): row = 32 fp16 + 8 pad = 40 fp16 = 20 words (80B).
#define RS 20
#define A_STAGE_WORDS (128 * RS)
#define B_STAGE_WORDS (128 * RS)
#define STAGE_WORDS (A_STAGE_WORDS + B_STAGE_WORDS)
#define NSTAGE 3
#define SMEM_BYTES (NSTAGE * STAGE_WORDS * 4)   // 61440

// ---------------- fused prep: convert_x | convert_w (+ticket reset) | hist ----------------
#define NB_CX 3125                     // NN*DD/8 / 256
#define NB_CW 256                      // (2*128*128 + 128*256) / 256
#define NB_H  ((NE + 255) / 256)       // 2344
__global__ void prep_kernel(const float* __restrict__ X,
                            const float* __restrict__ W1, const float* __restrict__ W2,
                            const int* __restrict__ edst) {
    int b = blockIdx.x;
    if (b < NB_CX) {
        // Xh = fp16(X), 8 elements per thread
        int i = b * 256 + threadIdx.x;
        const float4* src = reinterpret_cast<const float4*>(X) + (size_t)i * 2;
        float4 v0 = src[0], v1 = src[1];
        __half2 h0 = __floats2half2_rn(v0.x, v0.y);
        __half2 h1 = __floats2half2_rn(v0.z, v0.w);
        __half2 h2 = __floats2half2_rn(v1.x, v1.y);
        __half2 h3 = __floats2half2_rn(v1.z, v1.w);
        uint4 o;
        o.x = *reinterpret_cast<uint32_t*>(&h0);
        o.y = *reinterpret_cast<uint32_t*>(&h1);
        o.z = *reinterpret_cast<uint32_t*>(&h2);
        o.w = *reinterpret_cast<uint32_t*>(&h3);
        reinterpret_cast<uint4*>(g_Xh)[i] = o;
    } else if (b < NB_CX + NB_CW) {
        int idx = (b - NB_CX) * 256 + threadIdx.x;
        if (idx == 0) g_ticket = 0;
        if (idx < 2 * 128 * 128) {
            int h = idx >> 14;
            int rem = idx & 16383;
            int n = rem >> 7;
            int k = rem & 127;
            g_W1t[idx] = __float2half_rn(W1[(size_t)(h * 128 + k) * 128 + n]);
        } else {
            int j = idx - 2 * 128 * 128;
            int n = j >> 8;
            int k = j & 255;
            g_W2t[j] = __float2half_rn(W2[(size_t)k * 128 + n]);
        }
    } else {
        // histogram (g_cnt == 0 on entry: zero-init / re-zeroed by scan_kernel)
        int e = (b - NB_CX - NB_CW) * 256 + threadIdx.x;
        if (e < NE) atomicAdd(&g_cnt[__ldg(edst + e)], 1);
    }
}

// ---------------- single-kernel unordered scan (atomic ticket) ----------------
// Groups need only be contiguous per dst, not globally ordered, so each block
// allocates its span via one atomicAdd. Also snapshots deg and re-zeros cnt.
__global__ void scan_kernel() {
    __shared__ int sh[256];
    __shared__ int base;
    int i = blockIdx.x * 256 + threadIdx.x;
    int t = threadIdx.x;
    int v = (i < NN) ? g_cnt[i] : 0;
    sh[t] = v;
    __syncthreads();
#pragma unroll
    for (int d = 1; d < 256; d <<= 1) {
        int x = (t >= d) ? sh[t - d] : 0;
        __syncthreads();
        sh[t] += x;
        __syncthreads();
    }
    if (t == 255) base = atomicAdd(&g_ticket, sh[255]);
    __syncthreads();
    if (i < NN) {
        int exc = sh[t] - v + base;
        g_off[i] = exc;
        g_cur[i] = exc;
        g_deg[i] = v;
        g_cnt[i] = 0;   // restore invariant for next launch's histogram
    }
}

__global__ void scatter_kernel(const int* __restrict__ esrc, const int* __restrict__ edst) {
    int e = blockIdx.x * 256 + threadIdx.x;
    if (e < NE) {
        int d = __ldg(edst + e);
        int pos = atomicAdd(&g_cur[d], 1);
        g_srt[pos] = __ldg(esrc + e);
    }
}

// =======================================================================
// fp16 GEMM core (unchanged)
// =======================================================================

struct Frag { float acc[2][8][4]; };

__device__ __forceinline__ void gemm_compute_step(const uint32_t* As, const uint32_t* Bs,
                                                  int wm, int wn, int lane, Frag& F) {
    const int g = lane >> 2;
    const int t = lane & 3;
#pragma unroll
    for (int kg = 0; kg < 2; kg++) {
        const int kb = kg * 8;
        uint32_t a[2][4];
#pragma unroll
        for (int mt = 0; mt < 2; mt++) {
            int row = wm * 32 + mt * 16 + g;
            a[mt][0] = As[row * RS + kb + t];
            a[mt][1] = As[(row + 8) * RS + kb + t];
            a[mt][2] = As[row * RS + kb + t + 4];
            a[mt][3] = As[(row + 8) * RS + kb + t + 4];
        }
#pragma unroll
        for (int nt = 0; nt < 8; nt++) {
            int n = wn * 64 + nt * 8 + g;
            uint32_t b[2];
            b[0] = Bs[n * RS + kb + t];
            b[1] = Bs[n * RS + kb + t + 4];
            mma_f16(F.acc[0][nt], a[0], b);
            mma_f16(F.acc[1][nt], a[1], b);
        }
    }
}

__device__ __forceinline__ void gemm_issue_stage(uint32_t stage,
                                                 const __half* __restrict__ Ah, int m0, int ka,
                                                 const __half* __restrict__ Bt, int kb, int krow,
                                                 int tid) {
#pragma unroll
    for (int p = 0; p < 2; p++) {
        int id = tid + p * 256;
        int r  = id >> 2;
        int kc = id & 3;
        int gr = m0 + r;
        int ok = (gr < NN) ? 16 : 0;
        int grc = (gr < NN) ? gr : (NN - 1);
        cp16(stage + (r * RS + kc * 4) * 4, Ah + (size_t)grc * 128 + ka + kc * 8, ok);
    }
#pragma unroll
    for (int p = 0; p < 2; p++) {
        int id = tid + p * 256;
        int n  = id >> 2;
        int kc = id & 3;
        cp16(stage + (A_STAGE_WORDS + n * RS + kc * 4) * 4,
             Bt + (size_t)n * krow + kb + kc * 8, 16);
    }
    cp_commit();
}

// ---------------- GEMM 1: Yh[:, half*128:+128] = fp16(Xh @ W1half) ----------------
__global__ void __launch_bounds__(256, 2) proj_kernel() {
    extern __shared__ float sm[];
    const uint32_t smem_base = (uint32_t)__cvta_generic_to_shared(sm);

    const int half = blockIdx.y;
    const __half* Bt = g_W1t + half * (128 * 128);
    const int m0 = blockIdx.x * 128;

    const int tid  = threadIdx.x;
    const int lane = tid & 31;
    const int wid  = tid >> 5;
    const int wm   = wid & 3;
    const int wn   = wid >> 2;

    Frag F;
#pragma unroll
    for (int mt = 0; mt < 2; mt++)
#pragma unroll
        for (int nt = 0; nt < 8; nt++)
#pragma unroll
            for (int j = 0; j < 4; j++) F.acc[mt][nt][j] = 0.f;

    const int NS = 4;
    gemm_issue_stage(smem_base + 0 * STAGE_WORDS * 4, g_Xh, m0, 0,  Bt, 0,  128, tid);
    gemm_issue_stage(smem_base + 1 * STAGE_WORDS * 4, g_Xh, m0, 32, Bt, 32, 128, tid);

#pragma unroll
    for (int s = 0; s < NS; s++) {
        if (s + 1 < NS) cp_wait<1>(); else cp_wait<0>();
        __syncthreads();
        int nxt = s + 2;
        if (nxt < NS)
            gemm_issue_stage(smem_base + (nxt % NSTAGE) * STAGE_WORDS * 4,
                             g_Xh, m0, nxt * 32, Bt, nxt * 32, 128, tid);
        const uint32_t* stage = (const uint32_t*)sm + (s % NSTAGE) * STAGE_WORDS;
        gemm_compute_step(stage, stage + A_STAGE_WORDS, wm, wn, lane, F);
    }

    const int g = lane >> 2;
    const int t = lane & 3;
#pragma unroll
    for (int mt = 0; mt < 2; mt++) {
        int row0 = m0 + wm * 32 + mt * 16 + g;
#pragma unroll
        for (int nt = 0; nt < 8; nt++) {
            int col = wn * 64 + nt * 8 + 2 * t;
            if (row0 < NN) {
                __half2 v = __floats2half2_rn(F.acc[mt][nt][0], F.acc[mt][nt][1]);
                *reinterpret_cast<__half2*>(g_Yh + (size_t)row0 * 256 + half * 128 + col) = v;
            }
            if (row0 + 8 < NN) {
                __half2 v = __floats2half2_rn(F.acc[mt][nt][2], F.acc[mt][nt][3]);
                *reinterpret_cast<__half2*>(g_Yh + (size_t)(row0 + 8) * 256 + half * 128 + col) = v;
            }
        }
    }
}

// ---------------- Aggregate: one warp per dst node, fp32 register accumulation ----------------
__global__ void __launch_bounds__(256) aggregate_kernel(const float* __restrict__ b1) {
    int d = blockIdx.x * 8 + (threadIdx.x >> 5);
    if (d >= NN) return;
    int lane = threadIdx.x & 31;

    int base = g_off[d];
    int deg  = g_deg[d];

    float4 bb = reinterpret_cast<const float4*>(b1)[lane];
    uint2 ub = *(reinterpret_cast<const uint2*>(g_Yh + (size_t)d * 256 + 128) + lane);
    float2 b01 = __half22float2(*reinterpret_cast<__half2*>(&ub.x));
    float2 b23 = __half22float2(*reinterpret_cast<__half2*>(&ub.y));
    float c0 = b01.x + bb.x, c1 = b01.y + bb.y, c2 = b23.x + bb.z, c3 = b23.y + bb.w;

    float a0 = 0.f, a1 = 0.f, a2 = 0.f, a3 = 0.f;
#pragma unroll 2
    for (int i = 0; i < deg; i++) {
        int s = __ldg(g_srt + base + i);
        uint2 ua = *(reinterpret_cast<const uint2*>(g_Yh + (size_t)s * 256) + lane);
        float2 p01 = __half22float2(*reinterpret_cast<__half2*>(&ua.x));
        float2 p23 = __half22float2(*reinterpret_cast<__half2*>(&ua.y));
        a0 += fmaxf(p01.x + c0, 0.f);
        a1 += fmaxf(p01.y + c1, 0.f);
        a2 += fmaxf(p23.x + c2, 0.f);
        a3 += fmaxf(p23.y + c3, 0.f);
    }

    __half2 h0 = __floats2half2_rn(a0, a1);
    __half2 h1 = __floats2half2_rn(a2, a3);
    uint2 o;
    o.x = *reinterpret_cast<uint32_t*>(&h0);
    o.y = *reinterpret_cast<uint32_t*>(&h1);
    *(reinterpret_cast<uint2*>(g_aggh + (size_t)d * 128) + lane) = o;
}

// ---------------- GEMM 2 + epilogue: out = x + relu([Xh|aggh] @ W2 + b2) ----------------
__global__ void __launch_bounds__(256, 2) update_kernel(const float* __restrict__ X,
                                                        const float* __restrict__ b2,
                                                        float* __restrict__ out) {
    extern __shared__ float sm[];
    const uint32_t smem_base = (uint32_t)__cvta_generic_to_shared(sm);

    const int m0 = blockIdx.x * 128;

    const int tid  = threadIdx.x;
    const int lane = tid & 31;
    const int wid  = tid >> 5;
    const int wm   = wid & 3;
    const int wn   = wid >> 2;

    Frag F;
#pragma unroll
    for (int mt = 0; mt < 2; mt++)
#pragma unroll
        for (int nt = 0; nt < 8; nt++)
#pragma unroll
            for (int j = 0; j < 4; j++) F.acc[mt][nt][j] = 0.f;

    const int NS = 8;
    gemm_issue_stage(smem_base + 0 * STAGE_WORDS * 4, g_Xh, m0, 0,  g_W2t, 0,  256, tid);
    gemm_issue_stage(smem_base + 1 * STAGE_WORDS * 4, g_Xh, m0, 32, g_W2t, 32, 256, tid);

#pragma unroll
    for (int s = 0; s < NS; s++) {
        if (s + 1 < NS) cp_wait<1>(); else cp_wait<0>();
        __syncthreads();
        int nxt = s + 2;
        if (nxt < NS) {
            const __half* Ah = (nxt < 4) ? g_Xh : g_aggh;
            gemm_issue_stage(smem_base + (nxt % NSTAGE) * STAGE_WORDS * 4,
                             Ah, m0, (nxt * 32) & 127, g_W2t, nxt * 32, 256, tid);
        }
        const uint32_t* stage = (const uint32_t*)sm + (s % NSTAGE) * STAGE_WORDS;
        gemm_compute_step(stage, stage + A_STAGE_WORDS, wm, wn, lane, F);
    }

    const int g = lane >> 2;
    const int t = lane & 3;
#pragma unroll
    for (int mt = 0; mt < 2; mt++) {
        int row0 = m0 + wm * 32 + mt * 16 + g;
#pragma unroll
        for (int nt = 0; nt < 8; nt++) {
            int col = wn * 64 + nt * 8 + 2 * t;
            float2 bb = *reinterpret_cast<const float2*>(b2 + col);
            if (row0 < NN) {
                float2 x0 = *reinterpret_cast<const float2*>(X + (size_t)row0 * 128 + col);
                float2 v;
                v.x = x0.x + fmaxf(F.acc[mt][nt][0] + bb.x, 0.f);
                v.y = x0.y + fmaxf(F.acc[mt][nt][1] + bb.y, 0.f);
                *reinterpret_cast<float2*>(out + (size_t)row0 * 128 + col) = v;
            }
            if (row0 + 8 < NN) {
                float2 x1 = *reinterpret_cast<const float2*>(X + (size_t)(row0 + 8) * 128 + col);
                float2 v;
                v.x = x1.x + fmaxf(F.acc[mt][nt][2] + bb.x, 0.f);
                v.y = x1.y + fmaxf(F.acc[mt][nt][3] + bb.y, 0.f);
                *reinterpret_cast<float2*>(out + (size_t)(row0 + 8) * 128 + col) = v;
            }
        }
    }
}

extern "C" void kernel_launch(void* const* d_in, const int* in_sizes, int n_in,
                              void* d_out, int out_size) {
    const float* x    = (const float*)d_in[0];
    const int*   esrc = (const int*)d_in[1];
    const int*   edst = (const int*)d_in[2];
    const float* W1   = (const float*)d_in[3];
    const float* b1   = (const float*)d_in[4];
    const float* W2   = (const float*)d_in[5];
    const float* b2   = (const float*)d_in[6];
    float*       out  = (float*)d_out;

    (void)in_sizes; (void)n_in; (void)out_size;

    cudaFuncSetAttribute(proj_kernel,   cudaFuncAttributeMaxDynamicSharedMemorySize, SMEM_BYTES);
    cudaFuncSetAttribute(update_kernel, cudaFuncAttributeMaxDynamicSharedMemorySize, SMEM_BYTES);

    // 1. fused prep: Xh convert | W transpose+convert (+ticket reset) | dst histogram
    prep_kernel<<<NB_CX + NB_CW + NB_H, 256>>>(x, W1, W2, edst);
    // 2. unordered exclusive scan via atomic ticket (also snapshots deg, re-zeros cnt)
    scan_kernel<<<NBLK, 256>>>();
    // 3. group src indices by dst
    scatter_kernel<<<(NE + 255) / 256, 256>>>(esrc, edst);
    // 4. Yh = fp16(Xh @ [W1a | W1b])
    dim3 gProj((NN + 127) / 128, 2);
    proj_kernel<<<gProj, 256, SMEM_BYTES>>>();
    // 5. gather-aggregate per dst node (fp32 regs), write aggh fp16
    aggregate_kernel<<<(NN * 32 + 255) / 256, 256>>>(b1);
    // 6. out = x + relu([Xh|aggh] @ W2 + b2)
    update_kernel<<<(NN + 127) / 128, 256, SMEM_BYTES>>>(x, b2, out);
}

// round 14
// speedup vs baseline: 2.3346x; 1.0004x over previous
#include <cuda_runtime.h>
#include <cuda_fp16.h>
#include <cstdint>

#define NN 50000
#define NE 600000
#define DD 128
#define NBLK ((NN + 255) / 256)   // 196 scan blocks

// Scratch (device globals). Invariants maintained across launches:
//  - g_cnt == 0 at entry (zero-init at load; scan_kernel re-zeros after reading)
//  - g_ticket == 0 at entry to scan (prep_kernel zeros it earlier in same launch)
static __device__ __half g_Yh[(size_t)NN * 256];   // fp16 proj: 0:128 = x@W1a, 128:256 = x@W1b
static __device__ __half g_aggh[(size_t)NN * DD];  // fp16 aggregated messages
static __device__ __half g_Xh[(size_t)NN * DD];    // fp16 copy of X
static __device__ __half g_W1t[2 * 128 * 128];     // [half][n][k] fp16 (transposed W1)
static __device__ __half g_W2t[128 * 256];         // [n][k] fp16 (transposed W2)
static __device__ int    g_cnt[NN];
static __device__ int    g_off[NN];
static __device__ int    g_deg[NN];
static __device__ int    g_cur[NN];
static __device__ int    g_srt[NE];
static __device__ int    g_ticket;

// ---------------- helpers ----------------
__device__ __forceinline__ void mma_f16(float* d, const uint32_t* a, const uint32_t* b) {
    asm volatile(
        "mma.sync.aligned.m16n8k16.row.col.f32.f16.f16.f32 "
        "{%0,%1,%2,%3}, {%4,%5,%6,%7}, {%8,%9}, {%0,%1,%2,%3};"
        : "+f"(d[0]), "+f"(d[1]), "+f"(d[2]), "+f"(d[3])
        : "r"(a[0]), "r"(a[1]), "r"(a[2]), "r"(a[3]), "r"(b[0]), "r"(b[1]));
}

__device__ __forceinline__ void ldsm4(uint32_t& r0, uint32_t& r1, uint32_t& r2, uint32_t& r3,
                                      uint32_t addr) {
    asm volatile("ldmatrix.sync.aligned.m8n8.x4.shared.b16 {%0,%1,%2,%3}, [%4];"
                 : "=r"(r0), "=r"(r1), "=r"(r2), "=r"(r3) : "r"(addr));
}

__device__ __forceinline__ void cp16(uint32_t dst_smem, const void* src, int src_bytes) {
    asm volatile("cp.async.cg.shared.global [%0], [%1], 16, %2;"
                 :: "r"(dst_smem), "l"(src), "r"(src_bytes));
}
__device__ __forceinline__ void cp_commit() { asm volatile("cp.async.commit_group;"); }
template <int N>
__device__ __forceinline__ void cp_wait() { asm volatile("cp.async.wait_group %0;" :: "n"(N)); }

// SMEM layout (fp16, BK=32): row = 32 fp16 + 8 pad = 40 fp16 = 20 words (80B).
// Row stride 80B -> ldmatrix 8-row phases hit 8 distinct 4-word bank groups.
#define RS 20
#define A_STAGE_WORDS (128 * RS)
#define B_STAGE_WORDS (128 * RS)
#define STAGE_WORDS (A_STAGE_WORDS + B_STAGE_WORDS)
#define NSTAGE 3
#define SMEM_BYTES (NSTAGE * STAGE_WORDS * 4)   // 61440

// ---------------- fused prep: convert_x | convert_w (+ticket reset) | hist ----------------
#define NB_CX 3125
#define NB_CW 256
#define NB_H  ((NE + 255) / 256)
__global__ void prep_kernel(const float* __restrict__ X,
                            const float* __restrict__ W1, const float* __restrict__ W2,
                            const int* __restrict__ edst) {
    int b = blockIdx.x;
    if (b < NB_CX) {
        int i = b * 256 + threadIdx.x;
        const float4* src = reinterpret_cast<const float4*>(X) + (size_t)i * 2;
        float4 v0 = src[0], v1 = src[1];
        __half2 h0 = __floats2half2_rn(v0.x, v0.y);
        __half2 h1 = __floats2half2_rn(v0.z, v0.w);
        __half2 h2 = __floats2half2_rn(v1.x, v1.y);
        __half2 h3 = __floats2half2_rn(v1.z, v1.w);
        uint4 o;
        o.x = *reinterpret_cast<uint32_t*>(&h0);
        o.y = *reinterpret_cast<uint32_t*>(&h1);
        o.z = *reinterpret_cast<uint32_t*>(&h2);
        o.w = *reinterpret_cast<uint32_t*>(&h3);
        reinterpret_cast<uint4*>(g_Xh)[i] = o;
    } else if (b < NB_CX + NB_CW) {
        int idx = (b - NB_CX) * 256 + threadIdx.x;
        if (idx == 0) g_ticket = 0;
        if (idx < 2 * 128 * 128) {
            int h = idx >> 14;
            int rem = idx & 16383;
            int n = rem >> 7;
            int k = rem & 127;
            g_W1t[idx] = __float2half_rn(W1[(size_t)(h * 128 + k) * 128 + n]);
        } else {
            int j = idx - 2 * 128 * 128;
            int n = j >> 8;
            int k = j & 255;
            g_W2t[j] = __float2half_rn(W2[(size_t)k * 128 + n]);
        }
    } else {
        int e = (b - NB_CX - NB_CW) * 256 + threadIdx.x;
        if (e < NE) atomicAdd(&g_cnt[__ldg(edst + e)], 1);
    }
}

// ---------------- single-kernel unordered scan (atomic ticket) ----------------
__global__ void scan_kernel() {
    __shared__ int sh[256];
    __shared__ int base;
    int i = blockIdx.x * 256 + threadIdx.x;
    int t = threadIdx.x;
    int v = (i < NN) ? g_cnt[i] : 0;
    sh[t] = v;
    __syncthreads();
#pragma unroll
    for (int d = 1; d < 256; d <<= 1) {
        int x = (t >= d) ? sh[t - d] : 0;
        __syncthreads();
        sh[t] += x;
        __syncthreads();
    }
    if (t == 255) base = atomicAdd(&g_ticket, sh[255]);
    __syncthreads();
    if (i < NN) {
        int exc = sh[t] - v + base;
        g_off[i] = exc;
        g_cur[i] = exc;
        g_deg[i] = v;
        g_cnt[i] = 0;
    }
}

__global__ void scatter_kernel(const int* __restrict__ esrc, const int* __restrict__ edst) {
    int e = blockIdx.x * 256 + threadIdx.x;
    if (e < NE) {
        int d = __ldg(edst + e);
        int pos = atomicAdd(&g_cur[d], 1);
        g_srt[pos] = __ldg(esrc + e);
    }
}

// =======================================================================
// fp16 GEMM core with ldmatrix fragment loads
// =======================================================================

struct Frag { float acc[2][8][4]; };

__device__ __forceinline__ void gemm_compute_step(uint32_t AsAddr, uint32_t BsAddr,
                                                  int wm, int wn, int lane, Frag& F) {
    const int q  = lane >> 3;    // 0..3: ldmatrix tile index
    const int r8 = lane & 7;     // row within tile
#pragma unroll
    for (int kg = 0; kg < 2; kg++) {
        const int kb = kg * 8;   // word offset of this k16 slice
        uint32_t a[2][4];
#pragma unroll
        for (int mt = 0; mt < 2; mt++) {
            // tiles: q0=(m-lo,k-lo) q1=(m-hi,k-lo) q2=(m-lo,k-hi) q3=(m-hi,k-hi)
            int row = wm * 32 + mt * 16 + (q & 1) * 8 + r8;
            int kw  = kb + (q >> 1) * 4;
            ldsm4(a[mt][0], a[mt][1], a[mt][2], a[mt][3],
                  AsAddr + (uint32_t)(row * RS + kw) * 4);
        }
        uint32_t b[8][2];
#pragma unroll
        for (int np = 0; np < 4; np++) {
            // tiles: q0=(n-lo,k-lo) q1=(n-lo,k-hi) q2=(n-hi,k-lo) q3=(n-hi,k-hi)
            int n  = wn * 64 + np * 16 + (q >> 1) * 8 + r8;
            int kw = kb + (q & 1) * 4;
            uint32_t r0, r1, r2, r3;
            ldsm4(r0, r1, r2, r3, BsAddr + (uint32_t)(n * RS + kw) * 4);
            b[np * 2][0]     = r0;
            b[np * 2][1]     = r1;
            b[np * 2 + 1][0] = r2;
            b[np * 2 + 1][1] = r3;
        }
#pragma unroll
        for (int nt = 0; nt < 8; nt++) {
            mma_f16(F.acc[0][nt], a[0], b[nt]);
            mma_f16(F.acc[1][nt], a[1], b[nt]);
        }
    }
}

__device__ __forceinline__ void gemm_issue_stage(uint32_t stage,
                                                 const __half* __restrict__ Ah, int m0, int ka,
                                                 const __half* __restrict__ Bt, int kb, int krow,
                                                 int tid) {
#pragma unroll
    for (int p = 0; p < 2; p++) {
        int id = tid + p * 256;
        int r  = id >> 2;
        int kc = id & 3;
        int gr = m0 + r;
        int ok = (gr < NN) ? 16 : 0;
        int grc = (gr < NN) ? gr : (NN - 1);
        cp16(stage + (r * RS + kc * 4) * 4, Ah + (size_t)grc * 128 + ka + kc * 8, ok);
    }
#pragma unroll
    for (int p = 0; p < 2; p++) {
        int id = tid + p * 256;
        int n  = id >> 2;
        int kc = id & 3;
        cp16(stage + (A_STAGE_WORDS + n * RS + kc * 4) * 4,
             Bt + (size_t)n * krow + kb + kc * 8, 16);
    }
    cp_commit();
}

// ---------------- GEMM 1: Yh[:, half*128:+128] = fp16(Xh @ W1half) ----------------
__global__ void __launch_bounds__(256, 2) proj_kernel() {
    extern __shared__ float sm[];
    const uint32_t smem_base = (uint32_t)__cvta_generic_to_shared(sm);

    const int half = blockIdx.y;
    const __half* Bt = g_W1t + half * (128 * 128);
    const int m0 = blockIdx.x * 128;

    const int tid  = threadIdx.x;
    const int lane = tid & 31;
    const int wid  = tid >> 5;
    const int wm   = wid & 3;
    const int wn   = wid >> 2;

    Frag F;
#pragma unroll
    for (int mt = 0; mt < 2; mt++)
#pragma unroll
        for (int nt = 0; nt < 8; nt++)
#pragma unroll
            for (int j = 0; j < 4; j++) F.acc[mt][nt][j] = 0.f;

    const int NS = 4;
    gemm_issue_stage(smem_base + 0 * STAGE_WORDS * 4, g_Xh, m0, 0,  Bt, 0,  128, tid);
    gemm_issue_stage(smem_base + 1 * STAGE_WORDS * 4, g_Xh, m0, 32, Bt, 32, 128, tid);

#pragma unroll
    for (int s = 0; s < NS; s++) {
        if (s + 1 < NS) cp_wait<1>(); else cp_wait<0>();
        __syncthreads();
        int nxt = s + 2;
        if (nxt < NS)
            gemm_issue_stage(smem_base + (nxt % NSTAGE) * STAGE_WORDS * 4,
                             g_Xh, m0, nxt * 32, Bt, nxt * 32, 128, tid);
        uint32_t stage = smem_base + (s % NSTAGE) * STAGE_WORDS * 4;
        gemm_compute_step(stage, stage + A_STAGE_WORDS * 4, wm, wn, lane, F);
    }

    const int g = lane >> 2;
    const int t = lane & 3;
#pragma unroll
    for (int mt = 0; mt < 2; mt++) {
        int row0 = m0 + wm * 32 + mt * 16 + g;
#pragma unroll
        for (int nt = 0; nt < 8; nt++) {
            int col = wn * 64 + nt * 8 + 2 * t;
            if (row0 < NN) {
                __half2 v = __floats2half2_rn(F.acc[mt][nt][0], F.acc[mt][nt][1]);
                *reinterpret_cast<__half2*>(g_Yh + (size_t)row0 * 256 + half * 128 + col) = v;
            }
            if (row0 + 8 < NN) {
                __half2 v = __floats2half2_rn(F.acc[mt][nt][2], F.acc[mt][nt][3]);
                *reinterpret_cast<__half2*>(g_Yh + (size_t)(row0 + 8) * 256 + half * 128 + col) = v;
            }
        }
    }
}

// ---------------- Aggregate: one warp per dst node, fp32 register accumulation ----------------
__global__ void __launch_bounds__(256) aggregate_kernel(const float* __restrict__ b1) {
    int d = blockIdx.x * 8 + (threadIdx.x >> 5);
    if (d >= NN) return;
    int lane = threadIdx.x & 31;

    int base = g_off[d];
    int deg  = g_deg[d];

    float4 bb = reinterpret_cast<const float4*>(b1)[lane];
    uint2 ub = *(reinterpret_cast<const uint2*>(g_Yh + (size_t)d * 256 + 128) + lane);
    float2 b01 = __half22float2(*reinterpret_cast<__half2*>(&ub.x));
    float2 b23 = __half22float2(*reinterpret_cast<__half2*>(&ub.y));
    float c0 = b01.x + bb.x, c1 = b01.y + bb.y, c2 = b23.x + bb.z, c3 = b23.y + bb.w;

    float a0 = 0.f, a1 = 0.f, a2 = 0.f, a3 = 0.f;
#pragma unroll 2
    for (int i = 0; i < deg; i++) {
        int s = __ldg(g_srt + base + i);
        uint2 ua = *(reinterpret_cast<const uint2*>(g_Yh + (size_t)s * 256) + lane);
        float2 p01 = __half22float2(*reinterpret_cast<__half2*>(&ua.x));
        float2 p23 = __half22float2(*reinterpret_cast<__half2*>(&ua.y));
        a0 += fmaxf(p01.x + c0, 0.f);
        a1 += fmaxf(p01.y + c1, 0.f);
        a2 += fmaxf(p23.x + c2, 0.f);
        a3 += fmaxf(p23.y + c3, 0.f);
    }

    __half2 h0 = __floats2half2_rn(a0, a1);
    __half2 h1 = __floats2half2_rn(a2, a3);
    uint2 o;
    o.x = *reinterpret_cast<uint32_t*>(&h0);
    o.y = *reinterpret_cast<uint32_t*>(&h1);
    *(reinterpret_cast<uint2*>(g_aggh + (size_t)d * 128) + lane) = o;
}

// ---------------- GEMM 2 + epilogue: out = x + relu([Xh|aggh] @ W2 + b2) ----------------
__global__ void __launch_bounds__(256, 2) update_kernel(const float* __restrict__ X,
                                                        const float* __restrict__ b2,
                                                        float* __restrict__ out) {
    extern __shared__ float sm[];
    const uint32_t smem_base = (uint32_t)__cvta_generic_to_shared(sm);

    const int m0 = blockIdx.x * 128;

    const int tid  = threadIdx.x;
    const int lane = tid & 31;
    const int wid  = tid >> 5;
    const int wm   = wid & 3;
    const int wn   = wid >> 2;

    Frag F;
#pragma unroll
    for (int mt = 0; mt < 2; mt++)
#pragma unroll
        for (int nt = 0; nt < 8; nt++)
#pragma unroll
            for (int j = 0; j < 4; j++) F.acc[mt][nt][j] = 0.f;

    const int NS = 8;
    gemm_issue_stage(smem_base + 0 * STAGE_WORDS * 4, g_Xh, m0, 0,  g_W2t, 0,  256, tid);
    gemm_issue_stage(smem_base + 1 * STAGE_WORDS * 4, g_Xh, m0, 32, g_W2t, 32, 256, tid);

#pragma unroll
    for (int s = 0; s < NS; s++) {
        if (s + 1 < NS) cp_wait<1>(); else cp_wait<0>();
        __syncthreads();
        int nxt = s + 2;
        if (nxt < NS) {
            const __half* Ah = (nxt < 4) ? g_Xh : g_aggh;
            gemm_issue_stage(smem_base + (nxt % NSTAGE) * STAGE_WORDS * 4,
                             Ah, m0, (nxt * 32) & 127, g_W2t, nxt * 32, 256, tid);
        }
        uint32_t stage = smem_base + (s % NSTAGE) * STAGE_WORDS * 4;
        gemm_compute_step(stage, stage + A_STAGE_WORDS * 4, wm, wn, lane, F);
    }

    const int g = lane >> 2;
    const int t = lane & 3;
#pragma unroll
    for (int mt = 0; mt < 2; mt++) {
        int row0 = m0 + wm * 32 + mt * 16 + g;
#pragma unroll
        for (int nt = 0; nt < 8; nt++) {
            int col = wn * 64 + nt * 8 + 2 * t;
            float2 bb = *reinterpret_cast<const float2*>(b2 + col);
            if (row0 < NN) {
                float2 x0 = *reinterpret_cast<const float2*>(X + (size_t)row0 * 128 + col);
                float2 v;
                v.x = x0.x + fmaxf(F.acc[mt][nt][0] + bb.x, 0.f);
                v.y = x0.y + fmaxf(F.acc[mt][nt][1] + bb.y, 0.f);
                *reinterpret_cast<float2*>(out + (size_t)row0 * 128 + col) = v;
            }
            if (row0 + 8 < NN) {
                float2 x1 = *reinterpret_cast<const float2*>(X + (size_t)(row0 + 8) * 128 + col);
                float2 v;
                v.x = x1.x + fmaxf(F.acc[mt][nt][2] + bb.x, 0.f);
                v.y = x1.y + fmaxf(F.acc[mt][nt][3] + bb.y, 0.f);
                *reinterpret_cast<float2*>(out + (size_t)(row0 + 8) * 128 + col) = v;
            }
        }
    }
}

extern "C" void kernel_launch(void* const* d_in, const int* in_sizes, int n_in,
                              void* d_out, int out_size) {
    const float* x    = (const float*)d_in[0];
    const int*   esrc = (const int*)d_in[1];
    const int*   edst = (const int*)d_in[2];
    const float* W1   = (const float*)d_in[3];
    const float* b1   = (const float*)d_in[4];
    const float* W2   = (const float*)d_in[5];
    const float* b2   = (const float*)d_in[6];
    float*       out  = (float*)d_out;

    (void)in_sizes; (void)n_in; (void)out_size;

    cudaFuncSetAttribute(proj_kernel,   cudaFuncAttributeMaxDynamicSharedMemorySize, SMEM_BYTES);
    cudaFuncSetAttribute(update_kernel, cudaFuncAttributeMaxDynamicSharedMemorySize, SMEM_BYTES);

    // 1. fused prep: Xh convert | W transpose+convert (+ticket reset) | dst histogram
    prep_kernel<<<NB_CX + NB_CW + NB_H, 256>>>(x, W1, W2, edst);
    // 2. unordered exclusive scan via atomic ticket (snapshots deg, re-zeros cnt)
    scan_kernel<<<NBLK, 256>>>();
    // 3. group src indices by dst
    scatter_kernel<<<(NE + 255) / 256, 256>>>(esrc, edst);
    // 4. Yh = fp16(Xh @ [W1a | W1b])
    dim3 gProj((NN + 127) / 128, 2);
    proj_kernel<<<gProj, 256, SMEM_BYTES>>>();
    // 5. gather-aggregate per dst node (fp32 regs), write aggh fp16
    aggregate_kernel<<<(NN * 32 + 255) / 256, 256>>>(b1);
    // 6. out = x + relu([Xh|aggh] @ W2 + b2)
    update_kernel<<<(NN + 127) / 128, 256, SMEM_BYTES>>>(x, b2, out);
}

// round 16
// speedup vs baseline: 2.4458x; 1.0476x over previous
#include <cuda_runtime.h>
#include <cuda_fp16.h>
#include <cstdint>

#define NN 50000
#define NE 600000
#define DD 128
#define NBLK ((NN + 255) / 256)   // 196 scan blocks

// Scratch (device globals). Invariants maintained across launches:
//  - g_cnt == 0 at entry (zero-init at load; scan_kernel re-zeros after reading)
//  - g_ticket == 0 before scan (hist_kernel zeros it in the same stream branch)
static __device__ __half g_Yh[(size_t)NN * 256];   // fp16 proj: 0:128 = x@W1a, 128:256 = x@W1b
static __device__ __half g_aggh[(size_t)NN * DD];  // fp16 aggregated messages
static __device__ __half g_Xh[(size_t)NN * DD];    // fp16 copy of X
static __device__ __half g_W1t[2 * 128 * 128];     // [half][n][k] fp16 (transposed W1)
static __device__ __half g_W2t[128 * 256];         // [n][k] fp16 (transposed W2)
static __device__ int    g_cnt[NN];
static __device__ int    g_off[NN];
static __device__ int    g_deg[NN];
static __device__ int    g_cur[NN];
static __device__ int    g_srt[NE];
static __device__ int    g_ticket;

// ---------------- helpers ----------------
__device__ __forceinline__ void mma_f16(float* d, const uint32_t* a, const uint32_t* b) {
    asm volatile(
        "mma.sync.aligned.m16n8k16.row.col.f32.f16.f16.f32 "
        "{%0,%1,%2,%3}, {%4,%5,%6,%7}, {%8,%9}, {%0,%1,%2,%3};"
        : "+f"(d[0]), "+f"(d[1]), "+f"(d[2]), "+f"(d[3])
        : "r"(a[0]), "r"(a[1]), "r"(a[2]), "r"(a[3]), "r"(b[0]), "r"(b[1]));
}

__device__ __forceinline__ void ldsm4(uint32_t& r0, uint32_t& r1, uint32_t& r2, uint32_t& r3,
                                      uint32_t addr) {
    asm volatile("ldmatrix.sync.aligned.m8n8.x4.shared.b16 {%0,%1,%2,%3}, [%4];"
                 : "=r"(r0), "=r"(r1), "=r"(r2), "=r"(r3) : "r"(addr));
}

__device__ __forceinline__ void cp16(uint32_t dst_smem, const void* src, int src_bytes) {
    asm volatile("cp.async.cg.shared.global [%0], [%1], 16, %2;"
                 :: "r"(dst_smem), "l"(src), "r"(src_bytes));
}
__device__ __forceinline__ void cp_commit() { asm volatile("cp.async.commit_group;"); }
template <int N>
__device__ __forceinline__ void cp_wait() { asm volatile("cp.async.wait_group %0;" :: "n"(N)); }

// SMEM layout (fp16, BK=32): row = 32 fp16 + 8 pad = 40 fp16 = 20 words (80B).
#define RS 20
#define A_STAGE_WORDS (128 * RS)
#define B_STAGE_WORDS (128 * RS)
#define STAGE_WORDS (A_STAGE_WORDS + B_STAGE_WORDS)
#define NSTAGE 3
#define SMEM_BYTES (NSTAGE * STAGE_WORDS * 4)   // 61440

// ---------------- branch 1 prep: Xh convert | W transpose+convert ----------------
#define NB_CX 3125                     // NN*DD/8 / 256 (exact)
#define NB_CW 256                      // (2*128*128 + 128*256) / 256 (exact)
__global__ void convert_kernel(const float* __restrict__ X,
                               const float* __restrict__ W1, const float* __restrict__ W2) {
    int b = blockIdx.x;
    if (b < NB_CX) {
        int i = b * 256 + threadIdx.x;
        const float4* src = reinterpret_cast<const float4*>(X) + (size_t)i * 2;
        float4 v0 = src[0], v1 = src[1];
        __half2 h0 = __floats2half2_rn(v0.x, v0.y);
        __half2 h1 = __floats2half2_rn(v0.z, v0.w);
        __half2 h2 = __floats2half2_rn(v1.x, v1.y);
        __half2 h3 = __floats2half2_rn(v1.z, v1.w);
        uint4 o;
        o.x = *reinterpret_cast<uint32_t*>(&h0);
        o.y = *reinterpret_cast<uint32_t*>(&h1);
        o.z = *reinterpret_cast<uint32_t*>(&h2);
        o.w = *reinterpret_cast<uint32_t*>(&h3);
        reinterpret_cast<uint4*>(g_Xh)[i] = o;
    } else {
        int idx = (b - NB_CX) * 256 + threadIdx.x;
        if (idx < 2 * 128 * 128) {
            int h = idx >> 14;
            int rem = idx & 16383;
            int n = rem >> 7;
            int k = rem & 127;
            g_W1t[idx] = __float2half_rn(W1[(size_t)(h * 128 + k) * 128 + n]);
        } else {
            int j = idx - 2 * 128 * 128;
            int n = j >> 8;
            int k = j & 255;
            g_W2t[j] = __float2half_rn(W2[(size_t)k * 128 + n]);
        }
    }
}

// ---------------- branch 2: hist (+ticket reset) -> scan -> scatter ----------------
__global__ void hist_kernel(const int* __restrict__ edst) {
    int e = blockIdx.x * 256 + threadIdx.x;
    if (e == 0) g_ticket = 0;
    if (e < NE) atomicAdd(&g_cnt[__ldg(edst + e)], 1);
}

__global__ void scan_kernel() {
    __shared__ int sh[256];
    __shared__ int base;
    int i = blockIdx.x * 256 + threadIdx.x;
    int t = threadIdx.x;
    int v = (i < NN) ? g_cnt[i] : 0;
    sh[t] = v;
    __syncthreads();
#pragma unroll
    for (int d = 1; d < 256; d <<= 1) {
        int x = (t >= d) ? sh[t - d] : 0;
        __syncthreads();
        sh[t] += x;
        __syncthreads();
    }
    if (t == 255) base = atomicAdd(&g_ticket, sh[255]);
    __syncthreads();
    if (i < NN) {
        int exc = sh[t] - v + base;
        g_off[i] = exc;
        g_cur[i] = exc;
        g_deg[i] = v;
        g_cnt[i] = 0;   // restore invariant for next launch
    }
}

__global__ void scatter_kernel(const int* __restrict__ esrc, const int* __restrict__ edst) {
    int e = blockIdx.x * 256 + threadIdx.x;
    if (e < NE) {
        int d = __ldg(edst + e);
        int pos = atomicAdd(&g_cur[d], 1);
        g_srt[pos] = __ldg(esrc + e);
    }
}

// =======================================================================
// fp16 GEMM core with ldmatrix fragment loads (R13, known-good)
// =======================================================================

struct Frag { float acc[2][8][4]; };

__device__ __forceinline__ void gemm_compute_step(uint32_t AsAddr, uint32_t BsAddr,
                                                  int wm, int wn, int lane, Frag& F) {
    const int q  = lane >> 3;
    const int r8 = lane & 7;
#pragma unroll
    for (int kg = 0; kg < 2; kg++) {
        const int kb = kg * 8;
        uint32_t a[2][4];
#pragma unroll
        for (int mt = 0; mt < 2; mt++) {
            int row = wm * 32 + mt * 16 + (q & 1) * 8 + r8;
            int kw  = kb + (q >> 1) * 4;
            ldsm4(a[mt][0], a[mt][1], a[mt][2], a[mt][3],
                  AsAddr + (uint32_t)(row * RS + kw) * 4);
        }
        uint32_t b[8][2];
#pragma unroll
        for (int np = 0; np < 4; np++) {
            int n  = wn * 64 + np * 16 + (q >> 1) * 8 + r8;
            int kw = kb + (q & 1) * 4;
            uint32_t r0, r1, r2, r3;
            ldsm4(r0, r1, r2, r3, BsAddr + (uint32_t)(n * RS + kw) * 4);
            b[np * 2][0]     = r0;
            b[np * 2][1]     = r1;
            b[np * 2 + 1][0] = r2;
            b[np * 2 + 1][1] = r3;
        }
#pragma unroll
        for (int nt = 0; nt < 8; nt++) {
            mma_f16(F.acc[0][nt], a[0], b[nt]);
            mma_f16(F.acc[1][nt], a[1], b[nt]);
        }
    }
}

__device__ __forceinline__ void gemm_issue_stage(uint32_t stage,
                                                 const __half* __restrict__ Ah, int m0, int ka,
                                                 const __half* __restrict__ Bt, int kb, int krow,
                                                 int tid) {
#pragma unroll
    for (int p = 0; p < 2; p++) {
        int id = tid + p * 256;
        int r  = id >> 2;
        int kc = id & 3;
        int gr = m0 + r;
        int ok = (gr < NN) ? 16 : 0;
        int grc = (gr < NN) ? gr : (NN - 1);
        cp16(stage + (r * RS + kc * 4) * 4, Ah + (size_t)grc * 128 + ka + kc * 8, ok);
    }
#pragma unroll
    for (int p = 0; p < 2; p++) {
        int id = tid + p * 256;
        int n  = id >> 2;
        int kc = id & 3;
        cp16(stage + (A_STAGE_WORDS + n * RS + kc * 4) * 4,
             Bt + (size_t)n * krow + kb + kc * 8, 16);
    }
    cp_commit();
}

// ---------------- GEMM 1: Yh[:, half*128:+128] = fp16(Xh @ W1half) ----------------
__global__ void __launch_bounds__(256, 2) proj_kernel() {
    extern __shared__ float sm[];
    const uint32_t smem_base = (uint32_t)__cvta_generic_to_shared(sm);

    const int half = blockIdx.y;
    const __half* Bt = g_W1t + half * (128 * 128);
    const int m0 = blockIdx.x * 128;

    const int tid  = threadIdx.x;
    const int lane = tid & 31;
    const int wid  = tid >> 5;
    const int wm   = wid & 3;
    const int wn   = wid >> 2;

    Frag F;
#pragma unroll
    for (int mt = 0; mt < 2; mt++)
#pragma unroll
        for (int nt = 0; nt < 8; nt++)
#pragma unroll
            for (int j = 0; j < 4; j++) F.acc[mt][nt][j] = 0.f;

    const int NS = 4;
    gemm_issue_stage(smem_base + 0 * STAGE_WORDS * 4, g_Xh, m0, 0,  Bt, 0,  128, tid);
    gemm_issue_stage(smem_base + 1 * STAGE_WORDS * 4, g_Xh, m0, 32, Bt, 32, 128, tid);

#pragma unroll
    for (int s = 0; s < NS; s++) {
        if (s + 1 < NS) cp_wait<1>(); else cp_wait<0>();
        __syncthreads();
        int nxt = s + 2;
        if (nxt < NS)
            gemm_issue_stage(smem_base + (nxt % NSTAGE) * STAGE_WORDS * 4,
                             g_Xh, m0, nxt * 32, Bt, nxt * 32, 128, tid);
        uint32_t stage = smem_base + (s % NSTAGE) * STAGE_WORDS * 4;
        gemm_compute_step(stage, stage + A_STAGE_WORDS * 4, wm, wn, lane, F);
    }

    const int g = lane >> 2;
    const int t = lane & 3;
#pragma unroll
    for (int mt = 0; mt < 2; mt++) {
        int row0 = m0 + wm * 32 + mt * 16 + g;
#pragma unroll
        for (int nt = 0; nt < 8; nt++) {
            int col = wn * 64 + nt * 8 + 2 * t;
            if (row0 < NN) {
                __half2 v = __floats2half2_rn(F.acc[mt][nt][0], F.acc[mt][nt][1]);
                *reinterpret_cast<__half2*>(g_Yh + (size_t)row0 * 256 + half * 128 + col) = v;
            }
            if (row0 + 8 < NN) {
                __half2 v = __floats2half2_rn(F.acc[mt][nt][2], F.acc[mt][nt][3]);
                *reinterpret_cast<__half2*>(g_Yh + (size_t)(row0 + 8) * 256 + half * 128 + col) = v;
            }
        }
    }
}

// ---------------- Aggregate: one warp per dst node, fp32 register accumulation ----------------
__global__ void __launch_bounds__(256) aggregate_kernel(const float* __restrict__ b1) {
    int d = blockIdx.x * 8 + (threadIdx.x >> 5);
    if (d >= NN) return;
    int lane = threadIdx.x & 31;

    int base = g_off[d];
    int deg  = g_deg[d];

    float4 bb = reinterpret_cast<const float4*>(b1)[lane];
    uint2 ub = *(reinterpret_cast<const uint2*>(g_Yh + (size_t)d * 256 + 128) + lane);
    float2 b01 = __half22float2(*reinterpret_cast<__half2*>(&ub.x));
    float2 b23 = __half22float2(*reinterpret_cast<__half2*>(&ub.y));
    float c0 = b01.x + bb.x, c1 = b01.y + bb.y, c2 = b23.x + bb.z, c3 = b23.y + bb.w;

    float a0 = 0.f, a1 = 0.f, a2 = 0.f, a3 = 0.f;
#pragma unroll 2
    for (int i = 0; i < deg; i++) {
        int s = __ldg(g_srt + base + i);
        uint2 ua = *(reinterpret_cast<const uint2*>(g_Yh + (size_t)s * 256) + lane);
        float2 p01 = __half22float2(*reinterpret_cast<__half2*>(&ua.x));
        float2 p23 = __half22float2(*reinterpret_cast<__half2*>(&ua.y));
        a0 += fmaxf(p01.x + c0, 0.f);
        a1 += fmaxf(p01.y + c1, 0.f);
        a2 += fmaxf(p23.x + c2, 0.f);
        a3 += fmaxf(p23.y + c3, 0.f);
    }

    __half2 h0 = __floats2half2_rn(a0, a1);
    __half2 h1 = __floats2half2_rn(a2, a3);
    uint2 o;
    o.x = *reinterpret_cast<uint32_t*>(&h0);
    o.y = *reinterpret_cast<uint32_t*>(&h1);
    *(reinterpret_cast<uint2*>(g_aggh + (size_t)d * 128) + lane) = o;
}

// ---------------- GEMM 2 + epilogue: out = x + relu([Xh|aggh] @ W2 + b2) ----------------
__global__ void __launch_bounds__(256, 2) update_kernel(const float* __restrict__ X,
                                                        const float* __restrict__ b2,
                                                        float* __restrict__ out) {
    extern __shared__ float sm[];
    const uint32_t smem_base = (uint32_t)__cvta_generic_to_shared(sm);

    const int m0 = blockIdx.x * 128;

    const int tid  = threadIdx.x;
    const int lane = tid & 31;
    const int wid  = tid >> 5;
    const int wm   = wid & 3;
    const int wn   = wid >> 2;

    Frag F;
#pragma unroll
    for (int mt = 0; mt < 2; mt++)
#pragma unroll
        for (int nt = 0; nt < 8; nt++)
#pragma unroll
            for (int j = 0; j < 4; j++) F.acc[mt][nt][j] = 0.f;

    const int NS = 8;
    gemm_issue_stage(smem_base + 0 * STAGE_WORDS * 4, g_Xh, m0, 0,  g_W2t, 0,  256, tid);
    gemm_issue_stage(smem_base + 1 * STAGE_WORDS * 4, g_Xh, m0, 32, g_W2t, 32, 256, tid);

#pragma unroll
    for (int s = 0; s < NS; s++) {
        if (s + 1 < NS) cp_wait<1>(); else cp_wait<0>();
        __syncthreads();
        int nxt = s + 2;
        if (nxt < NS) {
            const __half* Ah = (nxt < 4) ? g_Xh : g_aggh;
            gemm_issue_stage(smem_base + (nxt % NSTAGE) * STAGE_WORDS * 4,
                             Ah, m0, (nxt * 32) & 127, g_W2t, nxt * 32, 256, tid);
        }
        uint32_t stage = smem_base + (s % NSTAGE) * STAGE_WORDS * 4;
        gemm_compute_step(stage, stage + A_STAGE_WORDS * 4, wm, wn, lane, F);
    }

    const int g = lane >> 2;
    const int t = lane & 3;
#pragma unroll
    for (int mt = 0; mt < 2; mt++) {
        int row0 = m0 + wm * 32 + mt * 16 + g;
#pragma unroll
        for (int nt = 0; nt < 8; nt++) {
            int col = wn * 64 + nt * 8 + 2 * t;
            float2 bb = *reinterpret_cast<const float2*>(b2 + col);
            if (row0 < NN) {
                float2 x0 = *reinterpret_cast<const float2*>(X + (size_t)row0 * 128 + col);
                float2 v;
                v.x = x0.x + fmaxf(F.acc[mt][nt][0] + bb.x, 0.f);
                v.y = x0.y + fmaxf(F.acc[mt][nt][1] + bb.y, 0.f);
                *reinterpret_cast<float2*>(out + (size_t)row0 * 128 + col) = v;
            }
            if (row0 + 8 < NN) {
                float2 x1 = *reinterpret_cast<const float2*>(X + (size_t)(row0 + 8) * 128 + col);
                float2 v;
                v.x = x1.x + fmaxf(F.acc[mt][nt][2] + bb.x, 0.f);
                v.y = x1.y + fmaxf(F.acc[mt][nt][3] + bb.y, 0.f);
                *reinterpret_cast<float2*>(out + (size_t)(row0 + 8) * 128 + col) = v;
            }
        }
    }
}

extern "C" void kernel_launch(void* const* d_in, const int* in_sizes, int n_in,
                              void* d_out, int out_size) {
    const float* x    = (const float*)d_in[0];
    const int*   esrc = (const int*)d_in[1];
    const int*   edst = (const int*)d_in[2];
    const float* W1   = (const float*)d_in[3];
    const float* b1   = (const float*)d_in[4];
    const float* W2   = (const float*)d_in[5];
    const float* b2   = (const float*)d_in[6];
    float*       out  = (float*)d_out;

    (void)in_sizes; (void)n_in; (void)out_size;

    // One-time host-side handles (no device memory involved; device work per
    // call is identical and deterministic). Created on the first (uncaptured)
    // correctness call; reused during graph capture.
    static cudaStream_t s2 = nullptr;
    static cudaEvent_t  evFork = nullptr, evJoin = nullptr;
    if (s2 == nullptr) {
        cudaStreamCreateWithFlags(&s2, cudaStreamNonBlocking);
        cudaEventCreateWithFlags(&evFork, cudaEventDisableTiming);
        cudaEventCreateWithFlags(&evJoin, cudaEventDisableTiming);
        cudaFuncSetAttribute(proj_kernel,   cudaFuncAttributeMaxDynamicSharedMemorySize, SMEM_BYTES);
        cudaFuncSetAttribute(update_kernel, cudaFuncAttributeMaxDynamicSharedMemorySize, SMEM_BYTES);
    }

    // Fork: branch 2 (edge sort chain) runs concurrently with branch 1
    // (operand convert + proj GEMM). They share no data until aggregate.
    cudaEventRecord(evFork, 0);
    cudaStreamWaitEvent(s2, evFork, 0);

    // Branch 2 (stream s2): hist (+ticket reset) -> unordered scan -> scatter
    hist_kernel<<<(NE + 255) / 256, 256, 0, s2>>>(edst);
    scan_kernel<<<NBLK, 256, 0, s2>>>();
    scatter_kernel<<<(NE + 255) / 256, 256, 0, s2>>>(esrc, edst);
    cudaEventRecord(evJoin, s2);

    // Branch 1 (main stream): fp16 operand prep, then proj GEMM
    convert_kernel<<<NB_CX + NB_CW, 256>>>(x, W1, W2);
    dim3 gProj((NN + 127) / 128, 2);
    proj_kernel<<<gProj, 256, SMEM_BYTES>>>();

    // Join: aggregate needs both Yh (branch 1) and g_srt/g_off/g_deg (branch 2)
    cudaStreamWaitEvent(0, evJoin, 0);
    aggregate_kernel<<<(NN * 32 + 255) / 256, 256>>>(b1);
    update_kernel<<<(NN + 127) / 128, 256, SMEM_BYTES>>>(x, b2, out);
}